// round 10
// baseline (speedup 1.0000x reference)
#include <cuda_runtime.h>
#include <cstdint>

#define N_NODES 50000
#define D 128
#define N_EDGES 500000
#define TILE_M 128
#define GBLK ((N_NODES + TILE_M - 1) / TILE_M)
#define NTHREADS 512

// Scratch (no cudaMalloc). H1/ZN never leave the CTA.
__device__ float g_bufH2[N_NODES * D];
__device__ float g_bufG1[N_NODES * D];

// ---- smem layout (bytes); tiles at float row-stride 132 ----
// W1 region becomes H1 after pass 1; W2 region becomes bw after pass 2.
#define SM_ZN  0        // 128*132*4 = 67584
#define SM_W1  67584
#define SM_W2  135168
#define SM_PAR 202752   // 512 floats
#define SM_RED 204800   // 512 floats (sum 256 + sq 256)
#define SM_TOT 206848

__device__ __forceinline__ float to_tf32(float x) {
    uint32_t u;
    asm("cvt.rna.tf32.f32 %0, %1;" : "=r"(u) : "f"(x));
    return __uint_as_float(u);
}

__device__ __forceinline__ void mma_tf32(float& d0, float& d1, float& d2, float& d3,
                                         float a0, float a1, float a2, float a3,
                                         float b0, float b1) {
    asm volatile(
        "mma.sync.aligned.m16n8k8.row.col.f32.tf32.tf32.f32 "
        "{%0,%1,%2,%3}, {%4,%5,%6,%7}, {%8,%9}, {%0,%1,%2,%3};"
        : "+f"(d0), "+f"(d1), "+f"(d2), "+f"(d3)
        : "r"(__float_as_uint(a0)), "r"(__float_as_uint(a1)),
          "r"(__float_as_uint(a2)), "r"(__float_as_uint(a3)),
          "r"(__float_as_uint(b0)), "r"(__float_as_uint(b1)));
}

__device__ __forceinline__ float warp_sum(float v) {
#pragma unroll
    for (int o = 16; o > 0; o >>= 1) v += __shfl_xor_sync(0xffffffffu, v, o);
    return v;
}

// Mainloop: warp tile 16 rows x 64 cols; acc[nt][4]. A,B at stride 132.
__device__ __forceinline__ void mma_pass(const float* __restrict__ As,
                                         const float* __restrict__ Bs,
                                         float acc[8][4],
                                         int wr, int wc, int q, int tig) {
#pragma unroll
    for (int nt = 0; nt < 8; nt++)
#pragma unroll
        for (int j = 0; j < 4; j++) acc[nt][j] = 0.f;
    const int ra = wr * 16 + q;
#pragma unroll 4
    for (int kk = 0; kk < 16; kk++) {
        int c = kk * 8 + tig;
        float a0 = As[ra * 132 + c];
        float a1 = As[(ra + 8) * 132 + c];
        float a2 = As[ra * 132 + c + 4];
        float a3 = As[(ra + 8) * 132 + c + 4];
#pragma unroll
        for (int nt = 0; nt < 8; nt++) {
            int n = wc * 64 + nt * 8 + q;
            mma_tf32(acc[nt][0], acc[nt][1], acc[nt][2], acc[nt][3],
                     a0, a1, a2, a3, Bs[n * 132 + c], Bs[n * 132 + c + 4]);
        }
    }
}

// relu+bias+LN epilogue. TO_SMEM: tf32 -> H1 smem region; else fp32 -> gmem.
// Internal __syncthreads (after red-store) also guarantees all warps finished
// the preceding mainloop before the H1-over-W1 smem writes happen.
template <bool TO_SMEM>
__device__ __forceinline__ void epilogue_ln(
    float acc[8][4], const float* __restrict__ s_bias,
    const float* __restrict__ s_nw, const float* __restrict__ s_nb,
    float* __restrict__ red_sum, float* __restrict__ red_sq,
    float* __restrict__ H1, float* __restrict__ gout,
    int row0, int nrows, int wr, int wc, int q, int tig) {
    float sums[2] = {0.f, 0.f}, sqs[2] = {0.f, 0.f};
#pragma unroll
    for (int nt = 0; nt < 8; nt++) {
        int c = wc * 64 + nt * 8 + 2 * tig;
        float x0 = fmaxf(acc[nt][0] + s_bias[c], 0.f);
        float x1 = fmaxf(acc[nt][1] + s_bias[c + 1], 0.f);
        float y0 = fmaxf(acc[nt][2] + s_bias[c], 0.f);
        float y1 = fmaxf(acc[nt][3] + s_bias[c + 1], 0.f);
        acc[nt][0] = x0; acc[nt][1] = x1; acc[nt][2] = y0; acc[nt][3] = y1;
        sums[0] += x0 + x1; sqs[0] += x0 * x0 + x1 * x1;
        sums[1] += y0 + y1; sqs[1] += y0 * y0 + y1 * y1;
    }
#pragma unroll
    for (int o = 1; o <= 2; o <<= 1) {
#pragma unroll
        for (int h = 0; h < 2; h++) {
            sums[h] += __shfl_xor_sync(0xffffffffu, sums[h], o);
            sqs[h]  += __shfl_xor_sync(0xffffffffu, sqs[h], o);
        }
    }
    if (tig == 0) {
#pragma unroll
        for (int h = 0; h < 2; h++) {
            int r = wr * 16 + q + h * 8;
            red_sum[wc * 128 + r] = sums[h];
            red_sq[wc * 128 + r]  = sqs[h];
        }
    }
    __syncthreads();
    float mu[2], rs[2];
#pragma unroll
    for (int h = 0; h < 2; h++) {
        int r = wr * 16 + q + h * 8;
        float ts = red_sum[r] + red_sum[128 + r];
        float tq = red_sq[r] + red_sq[128 + r];
        float m = ts * (1.0f / 128.0f);
        mu[h] = m;
        rs[h] = rsqrtf(tq * (1.0f / 128.0f) - m * m + 1e-5f);
    }
#pragma unroll
    for (int nt = 0; nt < 8; nt++) {
        int c = wc * 64 + nt * 8 + 2 * tig;
        float nw0 = s_nw[c], nw1 = s_nw[c + 1];
        float nb0 = s_nb[c], nb1 = s_nb[c + 1];
#pragma unroll
        for (int h = 0; h < 2; h++) {
            int r = wr * 16 + q + h * 8;
            float v0 = (acc[nt][2 * h]     - mu[h]) * rs[h] * nw0 + nb0;
            float v1 = (acc[nt][2 * h + 1] - mu[h]) * rs[h] * nw1 + nb1;
            if (TO_SMEM) {
                *reinterpret_cast<float2*>(&H1[r * 132 + c]) =
                    make_float2(to_tf32(v0), to_tf32(v1));
            } else {
                int gr = row0 + r;
                if (gr < nrows)
                    *reinterpret_cast<float2*>(gout + (size_t)gr * D + c) =
                        make_float2(v0, v1);
            }
        }
    }
}

__global__ void __launch_bounds__(NTHREADS, 1) fused_kernel(
    const float* __restrict__ z,
    const float* __restrict__ w1, const float* __restrict__ b1,
    const float* __restrict__ w2, const float* __restrict__ b2,
    const float* __restrict__ bw,
    const float* __restrict__ nw, const float* __restrict__ nb,
    float* __restrict__ h2_out, float* __restrict__ g1_out, int nrows) {
    extern __shared__ char smem[];
    float*  ZN  = reinterpret_cast<float*>(smem + SM_ZN);
    float*  W1s = reinterpret_cast<float*>(smem + SM_W1);   // -> H1 after pass 1
    float*  W2s = reinterpret_cast<float*>(smem + SM_W2);   // -> bw after pass 2
    float*  par = reinterpret_cast<float*>(smem + SM_PAR);
    float*  red_sum = reinterpret_cast<float*>(smem + SM_RED);
    float*  red_sq  = red_sum + 256;
    float4* ZN4 = reinterpret_cast<float4*>(ZN);
    float4* W14 = reinterpret_cast<float4*>(W1s);
    float4* W24 = reinterpret_cast<float4*>(W2s);

    const int tid  = threadIdx.x;
    const int lane = tid & 31;
    const int w    = tid >> 5;    // 0..15
    const int q    = lane >> 2;
    const int tig  = lane & 3;
    const int wr   = w & 7;       // row group (16 rows)
    const int wc   = w >> 3;      // col group (64 cols)
    const int row0 = blockIdx.x * TILE_M;

    // ---- stage z + W1 + W2 together (one deep-MLP batch) + params ----
#pragma unroll
    for (int i = 0; i < 8; i++) {
        int idx = tid + i * NTHREADS;
        int r = idx >> 5, c4 = idx & 31;
        float4 v = make_float4(0.f, 0.f, 0.f, 0.f);
        int gr = row0 + r;
        if (gr < nrows) v = reinterpret_cast<const float4*>(z)[(size_t)gr * 32 + c4];
        ZN4[r * 33 + c4] = v;
    }
#pragma unroll
    for (int i = 0; i < 8; i++) {
        int idx = tid + i * NTHREADS;
        int r = idx >> 5, c4 = idx & 31;
        float4 v = reinterpret_cast<const float4*>(w1)[idx];
        v.x = to_tf32(v.x); v.y = to_tf32(v.y); v.z = to_tf32(v.z); v.w = to_tf32(v.w);
        W14[r * 33 + c4] = v;
    }
#pragma unroll
    for (int i = 0; i < 8; i++) {
        int idx = tid + i * NTHREADS;
        int r = idx >> 5, c4 = idx & 31;
        float4 v = reinterpret_cast<const float4*>(w2)[idx];
        v.x = to_tf32(v.x); v.y = to_tf32(v.y); v.z = to_tf32(v.z); v.w = to_tf32(v.w);
        W24[r * 33 + c4] = v;
    }
    par[tid & 511] = (tid < 128) ? b1[tid]
                   : (tid < 256) ? b2[tid - 128]
                   : (tid < 384) ? nw[tid - 256]
                                 : nb[tid - 384];
    __syncthreads();

    float* s_b1 = par;
    float* s_b2 = par + 128;
    float* s_nw = par + 256;
    float* s_nb = par + 384;

    // ---- LN(z) in place, tf32 (warp w: rows w*8 .. w*8+7) ----
    {
        float4 w4  = reinterpret_cast<float4*>(s_nw)[lane];
        float4 nb4 = reinterpret_cast<float4*>(s_nb)[lane];
#pragma unroll
        for (int i = 0; i < 8; i++) {
            int r = w * 8 + i;
            float4 v = ZN4[r * 33 + lane];
            float s  = warp_sum(v.x + v.y + v.z + v.w);
            float sq = warp_sum(v.x * v.x + v.y * v.y + v.z * v.z + v.w * v.w);
            float mu = s * (1.0f / 128.0f);
            float rs = rsqrtf(sq * (1.0f / 128.0f) - mu * mu + 1e-5f);
            v.x = to_tf32((v.x - mu) * rs * w4.x + nb4.x);
            v.y = to_tf32((v.y - mu) * rs * w4.y + nb4.y);
            v.z = to_tf32((v.z - mu) * rs * w4.z + nb4.z);
            v.w = to_tf32((v.w - mu) * rs * w4.w + nb4.w);
            ZN4[r * 33 + lane] = v;
        }
    }
    __syncthreads();

    float acc[8][4];

    // ===== PASS 1: H1 = LN(relu(ZN @ W1^T + b1)) -> W1 smem region (tf32) ===
    mma_pass(ZN, W1s, acc, wr, wc, q, tig);
    // epilogue's internal sync guarantees all warps left the mainloop (done
    // reading W1) before H1 is written over the W1 region.
    epilogue_ln<true>(acc, s_b1, s_nw, s_nb, red_sum, red_sq, W1s, nullptr,
                      row0, nrows, wr, wc, q, tig);

    // ---- prefetch bw into registers: LDG latency hides behind mainloop 2 ----
    float bwreg[32];
#pragma unroll
    for (int i = 0; i < 32; i++) bwreg[i] = bw[tid + i * NTHREADS];

    __syncthreads();  // H1 writes visible; red arrays reusable

    // ===== PASS 2: H2 = LN(relu(ZN @ W2^T + b2)) -> gmem ====================
    mma_pass(ZN, W2s, acc, wr, wc, q, tig);
    __syncthreads();  // all warps done reading W2 -> safe to overwrite with bw
    // STS bw^T into W2 region: W2s[f][d] = bw[d][f] (regs already resident)
#pragma unroll
    for (int i = 0; i < 32; i++) {
        int idx = tid + i * NTHREADS;
        int d = idx >> 7, f = idx & 127;
        W2s[f * 132 + d] = to_tf32(bwreg[i]);
    }
    epilogue_ln<false>(acc, s_b2, s_nw, s_nb, red_sum, red_sq, nullptr, h2_out,
                       row0, nrows, wr, wc, q, tig);
    __syncthreads();  // bw STS visible to all warps

    // ===== PASS 3: G1 = H1 @ bil_w -> gmem ==================================
    mma_pass(W1s, W2s, acc, wr, wc, q, tig);
#pragma unroll
    for (int nt = 0; nt < 8; nt++) {
        int c = wc * 64 + nt * 8 + 2 * tig;
#pragma unroll
        for (int h = 0; h < 2; h++) {
            int gr = row0 + wr * 16 + q + h * 8;
            if (gr < nrows)
                *reinterpret_cast<float2*>(g1_out + (size_t)gr * D + c) =
                    make_float2(acc[nt][2 * h], acc[nt][2 * h + 1]);
        }
    }
}

// ---------------------------------------------------------------------------
// Edge kernel (frozen at R8 config): 8 edges/warp = 2 batches x 4 edges;
// 8 lanes per edge -> full 128B wavefronts, 16 independent L2-only loads/lane.
// ---------------------------------------------------------------------------
__global__ void __launch_bounds__(256) edge_kernel(
    const int* __restrict__ arcs,
    const float* __restrict__ G1,
    const float* __restrict__ H2,
    const float* __restrict__ bilb,
    float* __restrict__ out) {
    const int warp = (blockIdx.x * blockDim.x + threadIdx.x) >> 5;
    const int lane = threadIdx.x & 31;
    const int j    = lane >> 3;   // edge-in-batch (0..3)
    const int s    = lane & 7;    // sub-lane within edge
    const int e0   = warp * 8 + j;
    if (e0 >= N_EDGES) return;

    int2 a[2];
    a[0] = __ldg(reinterpret_cast<const int2*>(arcs) + e0);
    a[1] = __ldg(reinterpret_cast<const int2*>(arcs) + e0 + 4);

    float4 g[2][4], h[2][4];
#pragma unroll
    for (int b = 0; b < 2; b++) {
        const float4* g4 = reinterpret_cast<const float4*>(G1 + (size_t)a[b].x * D);
        const float4* h4 = reinterpret_cast<const float4*>(H2 + (size_t)a[b].y * D);
#pragma unroll
        for (int k = 0; k < 4; k++) {
            g[b][k] = __ldcg(g4 + s + 8 * k);
            h[b][k] = __ldcg(h4 + s + 8 * k);
        }
    }
#pragma unroll
    for (int b = 0; b < 2; b++) {
        float v = 0.f;
#pragma unroll
        for (int k = 0; k < 4; k++) {
            v += g[b][k].x * h[b][k].x;
            v += g[b][k].y * h[b][k].y;
            v += g[b][k].z * h[b][k].z;
            v += g[b][k].w * h[b][k].w;
        }
        v += __shfl_xor_sync(0xffffffffu, v, 1);
        v += __shfl_xor_sync(0xffffffffu, v, 2);
        v += __shfl_xor_sync(0xffffffffu, v, 4);
        if (s == 0) out[e0 + b * 4] = v + bilb[0];
    }
}

// ---------------------------------------------------------------------------
extern "C" void kernel_launch(void* const* d_in, const int* in_sizes, int n_in,
                              void* d_out, int out_size) {
    const float* z    = (const float*)d_in[0];
    const int*   arcs = (const int*)d_in[1];
    const float* w1   = (const float*)d_in[2];
    const float* b1   = (const float*)d_in[3];
    const float* w2   = (const float*)d_in[4];
    const float* b2   = (const float*)d_in[5];
    const float* bw   = (const float*)d_in[6];
    const float* bb   = (const float*)d_in[7];
    const float* nw   = (const float*)d_in[8];
    const float* nb   = (const float*)d_in[9];
    float*       out  = (float*)d_out;

    float *h2buf, *g1buf;
    cudaGetSymbolAddress((void**)&h2buf, g_bufH2);
    cudaGetSymbolAddress((void**)&g1buf, g_bufG1);

    cudaFuncSetAttribute(fused_kernel,
                         cudaFuncAttributeMaxDynamicSharedMemorySize, SM_TOT);

    fused_kernel<<<GBLK, NTHREADS, SM_TOT>>>(z, w1, b1, w2, b2, bw, nw, nb,
                                             h2buf, g1buf, N_NODES);
    // 8 edges per warp, 8 warps per block -> 64 edges per block
    edge_kernel<<<(N_EDGES + 63) / 64, 256>>>(arcs, g1buf, h2buf, bb, out);
}

// round 11
// speedup vs baseline: 1.3404x; 1.3404x over previous
#include <cuda_runtime.h>
#include <cuda_fp16.h>
#include <cstdint>

#define N_NODES 50000
#define D 128
#define N_EDGES 500000
#define TILE_M 128
#define GBLK ((N_NODES + TILE_M - 1) / TILE_M)
#define NTHREADS 256

// Scratch (no cudaMalloc). H1/ZN never leave the CTA.
__device__ float g_bufH2[N_NODES * D];
__device__ float g_bufG1[N_NODES * D];

// ---- smem (bytes). fp16 tiles, 136 halves/row (stride 68 words -> 4q+tig banks)
#define HS     136
#define TILE_B (128 * HS * 2)        // 34816
#define SM_ZN  0
#define SM_W1  34816                 // -> H1 after pass 1
#define SM_W2  69632                 // -> bw^T after pass 2
#define SM_PAR 104448                // 512 floats
#define SM_RED 106496                // 512 floats (sum 256 + sq 256)
#define SM_TOT 108544                // x2 CTAs = 217088 <= SM smem

__device__ __forceinline__ void mma_f16(float& d0, float& d1, float& d2, float& d3,
                                        uint32_t a0, uint32_t a1, uint32_t a2,
                                        uint32_t a3, uint32_t b0, uint32_t b1) {
    asm volatile(
        "mma.sync.aligned.m16n8k16.row.col.f32.f16.f16.f32 "
        "{%0,%1,%2,%3}, {%4,%5,%6,%7}, {%8,%9}, {%0,%1,%2,%3};"
        : "+f"(d0), "+f"(d1), "+f"(d2), "+f"(d3)
        : "r"(a0), "r"(a1), "r"(a2), "r"(a3), "r"(b0), "r"(b1));
}

__device__ __forceinline__ float warp_sum(float v) {
#pragma unroll
    for (int o = 16; o > 0; o >>= 1) v += __shfl_xor_sync(0xffffffffu, v, o);
    return v;
}

// Mainloop: warp tile 32 rows x 64 cols, fp16 operands, fp32 acc.
// A[m][k], B[n][k] in smem at HS-half row stride.
__device__ __forceinline__ void mma_pass(const __half* __restrict__ A,
                                         const __half* __restrict__ B,
                                         float acc[2][8][4],
                                         int wr, int wc, int q, int tig) {
#pragma unroll
    for (int rt = 0; rt < 2; rt++)
#pragma unroll
        for (int nt = 0; nt < 8; nt++)
#pragma unroll
            for (int j = 0; j < 4; j++) acc[rt][nt][j] = 0.f;
#pragma unroll
    for (int kk = 0; kk < 8; kk++) {
        int k0 = kk * 16 + 2 * tig;
        uint32_t a[2][4];
#pragma unroll
        for (int rt = 0; rt < 2; rt++) {
            int ra = wr * 32 + rt * 16 + q;
            a[rt][0] = *reinterpret_cast<const uint32_t*>(&A[ra * HS + k0]);
            a[rt][1] = *reinterpret_cast<const uint32_t*>(&A[(ra + 8) * HS + k0]);
            a[rt][2] = *reinterpret_cast<const uint32_t*>(&A[ra * HS + k0 + 8]);
            a[rt][3] = *reinterpret_cast<const uint32_t*>(&A[(ra + 8) * HS + k0 + 8]);
        }
#pragma unroll
        for (int nt = 0; nt < 8; nt++) {
            int n = wc * 64 + nt * 8 + q;
            uint32_t b0 = *reinterpret_cast<const uint32_t*>(&B[n * HS + k0]);
            uint32_t b1 = *reinterpret_cast<const uint32_t*>(&B[n * HS + k0 + 8]);
#pragma unroll
            for (int rt = 0; rt < 2; rt++)
                mma_f16(acc[rt][nt][0], acc[rt][nt][1], acc[rt][nt][2],
                        acc[rt][nt][3], a[rt][0], a[rt][1], a[rt][2], a[rt][3],
                        b0, b1);
        }
    }
}

// relu+bias+LN epilogue. TO_SMEM: fp16 -> H1 smem region; else fp32 -> gmem.
// Internal __syncthreads doubles as the "all warps left mainloop" fence.
template <bool TO_SMEM>
__device__ __forceinline__ void epilogue_ln(
    float acc[2][8][4], const float* __restrict__ s_bias,
    const float* __restrict__ s_nw, const float* __restrict__ s_nb,
    float* __restrict__ red_sum, float* __restrict__ red_sq,
    __half* __restrict__ H1, float* __restrict__ gout,
    int row0, int nrows, int wr, int wc, int q, int tig) {
    float sums[2][2], sqs[2][2];
#pragma unroll
    for (int rt = 0; rt < 2; rt++) {
        sums[rt][0] = sums[rt][1] = sqs[rt][0] = sqs[rt][1] = 0.f;
#pragma unroll
        for (int nt = 0; nt < 8; nt++) {
            int c = wc * 64 + nt * 8 + 2 * tig;
            float x0 = fmaxf(acc[rt][nt][0] + s_bias[c], 0.f);
            float x1 = fmaxf(acc[rt][nt][1] + s_bias[c + 1], 0.f);
            float y0 = fmaxf(acc[rt][nt][2] + s_bias[c], 0.f);
            float y1 = fmaxf(acc[rt][nt][3] + s_bias[c + 1], 0.f);
            acc[rt][nt][0] = x0; acc[rt][nt][1] = x1;
            acc[rt][nt][2] = y0; acc[rt][nt][3] = y1;
            sums[rt][0] += x0 + x1; sqs[rt][0] += x0 * x0 + x1 * x1;
            sums[rt][1] += y0 + y1; sqs[rt][1] += y0 * y0 + y1 * y1;
        }
    }
#pragma unroll
    for (int o = 1; o <= 2; o <<= 1)
#pragma unroll
        for (int rt = 0; rt < 2; rt++)
#pragma unroll
            for (int h = 0; h < 2; h++) {
                sums[rt][h] += __shfl_xor_sync(0xffffffffu, sums[rt][h], o);
                sqs[rt][h]  += __shfl_xor_sync(0xffffffffu, sqs[rt][h], o);
            }
    if (tig == 0) {
#pragma unroll
        for (int rt = 0; rt < 2; rt++)
#pragma unroll
            for (int h = 0; h < 2; h++) {
                int r = wr * 32 + rt * 16 + q + h * 8;
                red_sum[wc * 128 + r] = sums[rt][h];
                red_sq[wc * 128 + r]  = sqs[rt][h];
            }
    }
    __syncthreads();
    float mu[2][2], rs[2][2];
#pragma unroll
    for (int rt = 0; rt < 2; rt++)
#pragma unroll
        for (int h = 0; h < 2; h++) {
            int r = wr * 32 + rt * 16 + q + h * 8;
            float ts = red_sum[r] + red_sum[128 + r];
            float tq = red_sq[r] + red_sq[128 + r];
            float m = ts * (1.0f / 128.0f);
            mu[rt][h] = m;
            rs[rt][h] = rsqrtf(tq * (1.0f / 128.0f) - m * m + 1e-5f);
        }
#pragma unroll
    for (int nt = 0; nt < 8; nt++) {
        int c = wc * 64 + nt * 8 + 2 * tig;
        float nw0 = s_nw[c], nw1 = s_nw[c + 1];
        float nb0 = s_nb[c], nb1 = s_nb[c + 1];
#pragma unroll
        for (int rt = 0; rt < 2; rt++)
#pragma unroll
            for (int h = 0; h < 2; h++) {
                int r = wr * 32 + rt * 16 + q + h * 8;
                float v0 = (acc[rt][nt][2 * h]     - mu[rt][h]) * rs[rt][h] * nw0 + nb0;
                float v1 = (acc[rt][nt][2 * h + 1] - mu[rt][h]) * rs[rt][h] * nw1 + nb1;
                if (TO_SMEM) {
                    *reinterpret_cast<__half2*>(&H1[r * HS + c]) =
                        __floats2half2_rn(v0, v1);
                } else {
                    int gr = row0 + r;
                    if (gr < nrows)
                        *reinterpret_cast<float2*>(gout + (size_t)gr * D + c) =
                            make_float2(v0, v1);
                }
            }
    }
}

__global__ void __launch_bounds__(NTHREADS, 2) fused_kernel(
    const float* __restrict__ z,
    const float* __restrict__ w1, const float* __restrict__ b1,
    const float* __restrict__ w2, const float* __restrict__ b2,
    const float* __restrict__ bw,
    const float* __restrict__ nw, const float* __restrict__ nb,
    float* __restrict__ h2_out, float* __restrict__ g1_out, int nrows) {
    extern __shared__ char smem[];
    __half* ZNh = reinterpret_cast<__half*>(smem + SM_ZN);
    __half* W1h = reinterpret_cast<__half*>(smem + SM_W1);   // -> H1
    __half* W2h = reinterpret_cast<__half*>(smem + SM_W2);   // -> bw^T
    float*  par = reinterpret_cast<float*>(smem + SM_PAR);
    float*  red_sum = reinterpret_cast<float*>(smem + SM_RED);
    float*  red_sq  = red_sum + 256;

    const int tid  = threadIdx.x;
    const int lane = tid & 31;
    const int w    = tid >> 5;    // 0..7
    const int q    = lane >> 2;
    const int tig  = lane & 3;
    const int wr   = w & 3;       // 32-row group
    const int wc   = w >> 2;      // 64-col group
    const int row0 = blockIdx.x * TILE_M;

    // ---- params ----
    for (int idx = tid; idx < 512; idx += NTHREADS)
        par[idx] = (idx < 128)   ? b1[idx]
                 : (idx < 256)   ? b2[idx - 128]
                 : (idx < 384)   ? nw[idx - 256]
                                 : nb[idx - 384];

    // ---- stage W1, W2 as fp16 ----
#pragma unroll
    for (int i = 0; i < 16; i++) {
        int idx = tid + i * NTHREADS;
        int r = idx >> 5, c4 = idx & 31;   // c4: float4 group (4 halves)
        float4 v1 = reinterpret_cast<const float4*>(w1)[idx];
        float4 v2 = reinterpret_cast<const float4*>(w2)[idx];
        int off = r * HS + c4 * 4;
        *reinterpret_cast<__half2*>(&W1h[off])     = __floats2half2_rn(v1.x, v1.y);
        *reinterpret_cast<__half2*>(&W1h[off + 2]) = __floats2half2_rn(v1.z, v1.w);
        *reinterpret_cast<__half2*>(&W2h[off])     = __floats2half2_rn(v2.x, v2.y);
        *reinterpret_cast<__half2*>(&W2h[off + 2]) = __floats2half2_rn(v2.z, v2.w);
    }
    __syncthreads();   // par visible for LN below

    // ---- ZN = LN(z) staged directly to fp16 smem (warp w: 16 rows) ----
    {
        const float* s_nw = par + 256;
        const float* s_nb = par + 384;
        float4 w4  = reinterpret_cast<const float4*>(s_nw)[lane];
        float4 nb4 = reinterpret_cast<const float4*>(s_nb)[lane];
#pragma unroll
        for (int i = 0; i < 16; i++) {
            int r = w * 16 + i;
            int gr = row0 + r;
            float4 v = make_float4(0.f, 0.f, 0.f, 0.f);
            if (gr < nrows) v = reinterpret_cast<const float4*>(z)[(size_t)gr * 32 + lane];
            float s  = warp_sum(v.x + v.y + v.z + v.w);
            float sq = warp_sum(v.x * v.x + v.y * v.y + v.z * v.z + v.w * v.w);
            float mu = s * (1.0f / 128.0f);
            float rs = rsqrtf(sq * (1.0f / 128.0f) - mu * mu + 1e-5f);
            float o0 = (v.x - mu) * rs * w4.x + nb4.x;
            float o1 = (v.y - mu) * rs * w4.y + nb4.y;
            float o2 = (v.z - mu) * rs * w4.z + nb4.z;
            float o3 = (v.w - mu) * rs * w4.w + nb4.w;
            int off = r * HS + lane * 4;
            *reinterpret_cast<__half2*>(&ZNh[off])     = __floats2half2_rn(o0, o1);
            *reinterpret_cast<__half2*>(&ZNh[off + 2]) = __floats2half2_rn(o2, o3);
        }
    }
    __syncthreads();

    const float* s_b1 = par;
    const float* s_b2 = par + 128;
    const float* s_nw = par + 256;
    const float* s_nb = par + 384;

    float acc[2][8][4];

    // ===== PASS 1: H1 = LN(relu(ZN @ W1^T + b1)) -> W1 region (fp16) =====
    mma_pass(ZNh, W1h, acc, wr, wc, q, tig);
    epilogue_ln<true>(acc, s_b1, s_nw, s_nb, red_sum, red_sq, W1h, nullptr,
                      row0, nrows, wr, wc, q, tig);
    // no sync needed: pass 2 touches only ZN + W2

    // ===== PASS 2: H2 = LN(relu(ZN @ W2^T + b2)) -> gmem =====
    mma_pass(ZNh, W2h, acc, wr, wc, q, tig);
    __syncthreads();   // all warps done reading W2 (and epilogue-1 red reads)
    // restage W2 region <- bw^T fp16: W2h[f][d] = bw[d][f]
#pragma unroll
    for (int i = 0; i < 64; i++) {
        int idx = tid + i * NTHREADS;
        int d = idx >> 7, f = idx & 127;
        W2h[f * HS + d] = __float2half_rn(bw[idx]);
    }
    // epilogue's internal sync makes the bw STS visible before pass 3
    epilogue_ln<false>(acc, s_b2, s_nw, s_nb, red_sum, red_sq, nullptr, h2_out,
                       row0, nrows, wr, wc, q, tig);

    // ===== PASS 3: G1 = H1 @ bil_w -> gmem =====
    mma_pass(W1h, W2h, acc, wr, wc, q, tig);
#pragma unroll
    for (int nt = 0; nt < 8; nt++) {
        int c = wc * 64 + nt * 8 + 2 * tig;
#pragma unroll
        for (int rt = 0; rt < 2; rt++)
#pragma unroll
            for (int h = 0; h < 2; h++) {
                int gr = row0 + wr * 32 + rt * 16 + q + h * 8;
                if (gr < nrows)
                    *reinterpret_cast<float2*>(g1_out + (size_t)gr * D + c) =
                        make_float2(acc[rt][nt][2 * h], acc[rt][nt][2 * h + 1]);
            }
    }
}

// ---------------------------------------------------------------------------
// Edge kernel (frozen): 8 edges/warp = 2 batches x 4 edges; 8 lanes/edge.
// ---------------------------------------------------------------------------
__global__ void __launch_bounds__(256) edge_kernel(
    const int* __restrict__ arcs,
    const float* __restrict__ G1,
    const float* __restrict__ H2,
    const float* __restrict__ bilb,
    float* __restrict__ out) {
    const int warp = (blockIdx.x * blockDim.x + threadIdx.x) >> 5;
    const int lane = threadIdx.x & 31;
    const int j    = lane >> 3;
    const int s    = lane & 7;
    const int e0   = warp * 8 + j;
    if (e0 >= N_EDGES) return;

    int2 a[2];
    a[0] = __ldg(reinterpret_cast<const int2*>(arcs) + e0);
    a[1] = __ldg(reinterpret_cast<const int2*>(arcs) + e0 + 4);

    float4 g[2][4], h[2][4];
#pragma unroll
    for (int b = 0; b < 2; b++) {
        const float4* g4 = reinterpret_cast<const float4*>(G1 + (size_t)a[b].x * D);
        const float4* h4 = reinterpret_cast<const float4*>(H2 + (size_t)a[b].y * D);
#pragma unroll
        for (int k = 0; k < 4; k++) {
            g[b][k] = __ldcg(g4 + s + 8 * k);
            h[b][k] = __ldcg(h4 + s + 8 * k);
        }
    }
#pragma unroll
    for (int b = 0; b < 2; b++) {
        float v = 0.f;
#pragma unroll
        for (int k = 0; k < 4; k++) {
            v += g[b][k].x * h[b][k].x;
            v += g[b][k].y * h[b][k].y;
            v += g[b][k].z * h[b][k].z;
            v += g[b][k].w * h[b][k].w;
        }
        v += __shfl_xor_sync(0xffffffffu, v, 1);
        v += __shfl_xor_sync(0xffffffffu, v, 2);
        v += __shfl_xor_sync(0xffffffffu, v, 4);
        if (s == 0) out[e0 + b * 4] = v + bilb[0];
    }
}

// ---------------------------------------------------------------------------
extern "C" void kernel_launch(void* const* d_in, const int* in_sizes, int n_in,
                              void* d_out, int out_size) {
    const float* z    = (const float*)d_in[0];
    const int*   arcs = (const int*)d_in[1];
    const float* w1   = (const float*)d_in[2];
    const float* b1   = (const float*)d_in[3];
    const float* w2   = (const float*)d_in[4];
    const float* b2   = (const float*)d_in[5];
    const float* bw   = (const float*)d_in[6];
    const float* bb   = (const float*)d_in[7];
    const float* nw   = (const float*)d_in[8];
    const float* nb   = (const float*)d_in[9];
    float*       out  = (float*)d_out;

    float *h2buf, *g1buf;
    cudaGetSymbolAddress((void**)&h2buf, g_bufH2);
    cudaGetSymbolAddress((void**)&g1buf, g_bufG1);

    cudaFuncSetAttribute(fused_kernel,
                         cudaFuncAttributeMaxDynamicSharedMemorySize, SM_TOT);

    fused_kernel<<<GBLK, NTHREADS, SM_TOT>>>(z, w1, b1, w2, b2, bw, nw, nb,
                                             h2buf, g1buf, N_NODES);
    edge_kernel<<<(N_EDGES + 63) / 64, 256>>>(arcs, g1buf, h2buf, bb, out);
}

// round 12
// speedup vs baseline: 1.6094x; 1.2006x over previous
#include <cuda_runtime.h>
#include <cuda_fp16.h>
#include <cstdint>

#define N_NODES 50000
#define D 128
#define N_EDGES 500000
#define TILE_M 128
#define GBLK ((N_NODES + TILE_M - 1) / TILE_M)
#define NTHREADS 256

// Scratch (no cudaMalloc). H2/G1 stored fp16 (halves edge-gather traffic).
__device__ __half g_bufH2[N_NODES * D];
__device__ __half g_bufG1[N_NODES * D];

// ---- smem (bytes). fp16 tiles, 136 halves/row ----
#define HS     136
#define SM_ZN  0
#define SM_W1  34816                 // -> H1 after pass 1
#define SM_W2  69632                 // -> bw^T after pass 2
#define SM_PAR 104448                // 512 floats
#define SM_RED 106496                // 512 floats (sum 256 + sq 256)
#define SM_TOT 108544                // x2 CTAs/SM

__device__ __forceinline__ void mma_f16(float& d0, float& d1, float& d2, float& d3,
                                        uint32_t a0, uint32_t a1, uint32_t a2,
                                        uint32_t a3, uint32_t b0, uint32_t b1) {
    asm volatile(
        "mma.sync.aligned.m16n8k16.row.col.f32.f16.f16.f32 "
        "{%0,%1,%2,%3}, {%4,%5,%6,%7}, {%8,%9}, {%0,%1,%2,%3};"
        : "+f"(d0), "+f"(d1), "+f"(d2), "+f"(d3)
        : "r"(a0), "r"(a1), "r"(a2), "r"(a3), "r"(b0), "r"(b1));
}

__device__ __forceinline__ float warp_sum(float v) {
#pragma unroll
    for (int o = 16; o > 0; o >>= 1) v += __shfl_xor_sync(0xffffffffu, v, o);
    return v;
}

// Mainloop: warp tile 32 rows x 64 cols, fp16 operands, fp32 acc.
__device__ __forceinline__ void mma_pass(const __half* __restrict__ A,
                                         const __half* __restrict__ B,
                                         float acc[2][8][4],
                                         int wr, int wc, int q, int tig) {
#pragma unroll
    for (int rt = 0; rt < 2; rt++)
#pragma unroll
        for (int nt = 0; nt < 8; nt++)
#pragma unroll
            for (int j = 0; j < 4; j++) acc[rt][nt][j] = 0.f;
#pragma unroll
    for (int kk = 0; kk < 8; kk++) {
        int k0 = kk * 16 + 2 * tig;
        uint32_t a[2][4];
#pragma unroll
        for (int rt = 0; rt < 2; rt++) {
            int ra = wr * 32 + rt * 16 + q;
            a[rt][0] = *reinterpret_cast<const uint32_t*>(&A[ra * HS + k0]);
            a[rt][1] = *reinterpret_cast<const uint32_t*>(&A[(ra + 8) * HS + k0]);
            a[rt][2] = *reinterpret_cast<const uint32_t*>(&A[ra * HS + k0 + 8]);
            a[rt][3] = *reinterpret_cast<const uint32_t*>(&A[(ra + 8) * HS + k0 + 8]);
        }
#pragma unroll
        for (int nt = 0; nt < 8; nt++) {
            int n = wc * 64 + nt * 8 + q;
            uint32_t b0 = *reinterpret_cast<const uint32_t*>(&B[n * HS + k0]);
            uint32_t b1 = *reinterpret_cast<const uint32_t*>(&B[n * HS + k0 + 8]);
#pragma unroll
            for (int rt = 0; rt < 2; rt++)
                mma_f16(acc[rt][nt][0], acc[rt][nt][1], acc[rt][nt][2],
                        acc[rt][nt][3], a[rt][0], a[rt][1], a[rt][2], a[rt][3],
                        b0, b1);
        }
    }
}

// relu+bias+LN epilogue. TO_SMEM: fp16 -> H1 smem region; else fp16 -> gmem.
template <bool TO_SMEM>
__device__ __forceinline__ void epilogue_ln(
    float acc[2][8][4], const float* __restrict__ s_bias,
    const float* __restrict__ s_nw, const float* __restrict__ s_nb,
    float* __restrict__ red_sum, float* __restrict__ red_sq,
    __half* __restrict__ H1, __half* __restrict__ gout,
    int row0, int nrows, int wr, int wc, int q, int tig) {
    float sums[2][2], sqs[2][2];
#pragma unroll
    for (int rt = 0; rt < 2; rt++) {
        sums[rt][0] = sums[rt][1] = sqs[rt][0] = sqs[rt][1] = 0.f;
#pragma unroll
        for (int nt = 0; nt < 8; nt++) {
            int c = wc * 64 + nt * 8 + 2 * tig;
            float x0 = fmaxf(acc[rt][nt][0] + s_bias[c], 0.f);
            float x1 = fmaxf(acc[rt][nt][1] + s_bias[c + 1], 0.f);
            float y0 = fmaxf(acc[rt][nt][2] + s_bias[c], 0.f);
            float y1 = fmaxf(acc[rt][nt][3] + s_bias[c + 1], 0.f);
            acc[rt][nt][0] = x0; acc[rt][nt][1] = x1;
            acc[rt][nt][2] = y0; acc[rt][nt][3] = y1;
            sums[rt][0] += x0 + x1; sqs[rt][0] += x0 * x0 + x1 * x1;
            sums[rt][1] += y0 + y1; sqs[rt][1] += y0 * y0 + y1 * y1;
        }
    }
#pragma unroll
    for (int o = 1; o <= 2; o <<= 1)
#pragma unroll
        for (int rt = 0; rt < 2; rt++)
#pragma unroll
            for (int h = 0; h < 2; h++) {
                sums[rt][h] += __shfl_xor_sync(0xffffffffu, sums[rt][h], o);
                sqs[rt][h]  += __shfl_xor_sync(0xffffffffu, sqs[rt][h], o);
            }
    if (tig == 0) {
#pragma unroll
        for (int rt = 0; rt < 2; rt++)
#pragma unroll
            for (int h = 0; h < 2; h++) {
                int r = wr * 32 + rt * 16 + q + h * 8;
                red_sum[wc * 128 + r] = sums[rt][h];
                red_sq[wc * 128 + r]  = sqs[rt][h];
            }
    }
    __syncthreads();
    float mu[2][2], rs[2][2];
#pragma unroll
    for (int rt = 0; rt < 2; rt++)
#pragma unroll
        for (int h = 0; h < 2; h++) {
            int r = wr * 32 + rt * 16 + q + h * 8;
            float ts = red_sum[r] + red_sum[128 + r];
            float tq = red_sq[r] + red_sq[128 + r];
            float m = ts * (1.0f / 128.0f);
            mu[rt][h] = m;
            rs[rt][h] = rsqrtf(tq * (1.0f / 128.0f) - m * m + 1e-5f);
        }
#pragma unroll
    for (int nt = 0; nt < 8; nt++) {
        int c = wc * 64 + nt * 8 + 2 * tig;
        float nw0 = s_nw[c], nw1 = s_nw[c + 1];
        float nb0 = s_nb[c], nb1 = s_nb[c + 1];
#pragma unroll
        for (int rt = 0; rt < 2; rt++)
#pragma unroll
            for (int h = 0; h < 2; h++) {
                int r = wr * 32 + rt * 16 + q + h * 8;
                float v0 = (acc[rt][nt][2 * h]     - mu[rt][h]) * rs[rt][h] * nw0 + nb0;
                float v1 = (acc[rt][nt][2 * h + 1] - mu[rt][h]) * rs[rt][h] * nw1 + nb1;
                if (TO_SMEM) {
                    *reinterpret_cast<__half2*>(&H1[r * HS + c]) =
                        __floats2half2_rn(v0, v1);
                } else {
                    int gr = row0 + r;
                    if (gr < nrows)
                        *reinterpret_cast<__half2*>(gout + (size_t)gr * D + c) =
                            __floats2half2_rn(v0, v1);
                }
            }
    }
}

__global__ void __launch_bounds__(NTHREADS, 2) fused_kernel(
    const float* __restrict__ z,
    const float* __restrict__ w1, const float* __restrict__ b1,
    const float* __restrict__ w2, const float* __restrict__ b2,
    const float* __restrict__ bw,
    const float* __restrict__ nw, const float* __restrict__ nb,
    __half* __restrict__ h2_out, __half* __restrict__ g1_out, int nrows) {
    extern __shared__ char smem[];
    __half* ZNh = reinterpret_cast<__half*>(smem + SM_ZN);
    __half* W1h = reinterpret_cast<__half*>(smem + SM_W1);   // -> H1
    __half* W2h = reinterpret_cast<__half*>(smem + SM_W2);   // -> bw^T
    float*  par = reinterpret_cast<float*>(smem + SM_PAR);
    float*  red_sum = reinterpret_cast<float*>(smem + SM_RED);
    float*  red_sq  = red_sum + 256;

    const int tid  = threadIdx.x;
    const int lane = tid & 31;
    const int w    = tid >> 5;    // 0..7
    const int q    = lane >> 2;
    const int tig  = lane & 3;
    const int wr   = w & 3;       // 32-row group
    const int wc   = w >> 2;      // 64-col group
    const int row0 = blockIdx.x * TILE_M;

    // ---- params ----
    for (int idx = tid; idx < 512; idx += NTHREADS)
        par[idx] = (idx < 128)   ? b1[idx]
                 : (idx < 256)   ? b2[idx - 128]
                 : (idx < 384)   ? nw[idx - 256]
                                 : nb[idx - 384];

    // ---- stage W1, W2 as fp16 ----
#pragma unroll
    for (int i = 0; i < 16; i++) {
        int idx = tid + i * NTHREADS;
        int r = idx >> 5, c4 = idx & 31;
        float4 v1 = reinterpret_cast<const float4*>(w1)[idx];
        float4 v2 = reinterpret_cast<const float4*>(w2)[idx];
        int off = r * HS + c4 * 4;
        *reinterpret_cast<__half2*>(&W1h[off])     = __floats2half2_rn(v1.x, v1.y);
        *reinterpret_cast<__half2*>(&W1h[off + 2]) = __floats2half2_rn(v1.z, v1.w);
        *reinterpret_cast<__half2*>(&W2h[off])     = __floats2half2_rn(v2.x, v2.y);
        *reinterpret_cast<__half2*>(&W2h[off + 2]) = __floats2half2_rn(v2.z, v2.w);
    }
    __syncthreads();   // par visible for LN below

    // ---- ZN = LN(z) staged directly to fp16 smem (warp w: 16 rows) ----
    {
        const float* s_nw = par + 256;
        const float* s_nb = par + 384;
        float4 w4  = reinterpret_cast<const float4*>(s_nw)[lane];
        float4 nb4 = reinterpret_cast<const float4*>(s_nb)[lane];
#pragma unroll
        for (int i = 0; i < 16; i++) {
            int r = w * 16 + i;
            int gr = row0 + r;
            float4 v = make_float4(0.f, 0.f, 0.f, 0.f);
            if (gr < nrows) v = reinterpret_cast<const float4*>(z)[(size_t)gr * 32 + lane];
            float s  = warp_sum(v.x + v.y + v.z + v.w);
            float sq = warp_sum(v.x * v.x + v.y * v.y + v.z * v.z + v.w * v.w);
            float mu = s * (1.0f / 128.0f);
            float rs = rsqrtf(sq * (1.0f / 128.0f) - mu * mu + 1e-5f);
            float o0 = (v.x - mu) * rs * w4.x + nb4.x;
            float o1 = (v.y - mu) * rs * w4.y + nb4.y;
            float o2 = (v.z - mu) * rs * w4.z + nb4.z;
            float o3 = (v.w - mu) * rs * w4.w + nb4.w;
            int off = r * HS + lane * 4;
            *reinterpret_cast<__half2*>(&ZNh[off])     = __floats2half2_rn(o0, o1);
            *reinterpret_cast<__half2*>(&ZNh[off + 2]) = __floats2half2_rn(o2, o3);
        }
    }
    __syncthreads();

    const float* s_b1 = par;
    const float* s_b2 = par + 128;
    const float* s_nw = par + 256;
    const float* s_nb = par + 384;

    float acc[2][8][4];

    // ===== PASS 1: H1 = LN(relu(ZN @ W1^T + b1)) -> W1 region (fp16) =====
    mma_pass(ZNh, W1h, acc, wr, wc, q, tig);
    epilogue_ln<true>(acc, s_b1, s_nw, s_nb, red_sum, red_sq, W1h, nullptr,
                      row0, nrows, wr, wc, q, tig);

    // ===== PASS 2: H2 = LN(relu(ZN @ W2^T + b2)) -> gmem (fp16) =====
    mma_pass(ZNh, W2h, acc, wr, wc, q, tig);
    __syncthreads();   // all warps done reading W2
    // restage W2 region <- bw^T fp16: W2h[f][d] = bw[d][f]
#pragma unroll
    for (int i = 0; i < 64; i++) {
        int idx = tid + i * NTHREADS;
        int d = idx >> 7, f = idx & 127;
        W2h[f * HS + d] = __float2half_rn(bw[idx]);
    }
    epilogue_ln<false>(acc, s_b2, s_nw, s_nb, red_sum, red_sq, nullptr, h2_out,
                       row0, nrows, wr, wc, q, tig);

    // ===== PASS 3: G1 = H1 @ bil_w -> gmem (fp16) =====
    mma_pass(W1h, W2h, acc, wr, wc, q, tig);
#pragma unroll
    for (int nt = 0; nt < 8; nt++) {
        int c = wc * 64 + nt * 8 + 2 * tig;
#pragma unroll
        for (int rt = 0; rt < 2; rt++)
#pragma unroll
            for (int h = 0; h < 2; h++) {
                int gr = row0 + wr * 32 + rt * 16 + q + h * 8;
                if (gr < nrows)
                    *reinterpret_cast<__half2*>(g1_out + (size_t)gr * D + c) =
                        __floats2half2_rn(acc[rt][nt][2 * h], acc[rt][nt][2 * h + 1]);
            }
    }
}

// ---------------------------------------------------------------------------
// Edge kernel v5 (fp16 gathers): 16 edges/warp = 4 batches x 4 edges;
// 8 lanes/edge. fp16 row = 256B = 16 float4; lane s loads chunks s, s+8 of
// each row -> full 128B wavefronts, 16 independent L2-only loads per lane.
// N_EDGES % 16 == 0 -> warps all-live or all-dead.
// ---------------------------------------------------------------------------
__global__ void __launch_bounds__(256) edge_kernel(
    const int* __restrict__ arcs,
    const __half* __restrict__ G1,
    const __half* __restrict__ H2,
    const float* __restrict__ bilb,
    float* __restrict__ out) {
    const int warp = (blockIdx.x * blockDim.x + threadIdx.x) >> 5;
    const int lane = threadIdx.x & 31;
    const int j    = lane >> 3;   // edge-in-batch (0..3)
    const int s    = lane & 7;    // sub-lane within edge
    const int e0   = warp * 16 + j;
    if (e0 >= N_EDGES) return;

    int2 a[4];
#pragma unroll
    for (int b = 0; b < 4; b++)
        a[b] = __ldg(reinterpret_cast<const int2*>(arcs) + e0 + 4 * b);

    float4 g[4][2], h[4][2];
#pragma unroll
    for (int b = 0; b < 4; b++) {
        const float4* g4 = reinterpret_cast<const float4*>(G1 + (size_t)a[b].x * D);
        const float4* h4 = reinterpret_cast<const float4*>(H2 + (size_t)a[b].y * D);
        g[b][0] = __ldcg(g4 + s);
        g[b][1] = __ldcg(g4 + s + 8);
        h[b][0] = __ldcg(h4 + s);
        h[b][1] = __ldcg(h4 + s + 8);
    }
#pragma unroll
    for (int b = 0; b < 4; b++) {
        float v = 0.f;
#pragma unroll
        for (int p = 0; p < 2; p++) {
            const __half2* gh = reinterpret_cast<const __half2*>(&g[b][p]);
            const __half2* hh = reinterpret_cast<const __half2*>(&h[b][p]);
#pragma unroll
            for (int k = 0; k < 4; k++) {
                float2 gf = __half22float2(gh[k]);
                float2 hf = __half22float2(hh[k]);
                v += gf.x * hf.x + gf.y * hf.y;
            }
        }
        v += __shfl_xor_sync(0xffffffffu, v, 1);
        v += __shfl_xor_sync(0xffffffffu, v, 2);
        v += __shfl_xor_sync(0xffffffffu, v, 4);
        if (s == 0) out[e0 + 4 * b] = v + bilb[0];
    }
}

// ---------------------------------------------------------------------------
extern "C" void kernel_launch(void* const* d_in, const int* in_sizes, int n_in,
                              void* d_out, int out_size) {
    const float* z    = (const float*)d_in[0];
    const int*   arcs = (const int*)d_in[1];
    const float* w1   = (const float*)d_in[2];
    const float* b1   = (const float*)d_in[3];
    const float* w2   = (const float*)d_in[4];
    const float* b2   = (const float*)d_in[5];
    const float* bw   = (const float*)d_in[6];
    const float* bb   = (const float*)d_in[7];
    const float* nw   = (const float*)d_in[8];
    const float* nb   = (const float*)d_in[9];
    float*       out  = (float*)d_out;

    __half *h2buf, *g1buf;
    cudaGetSymbolAddress((void**)&h2buf, g_bufH2);
    cudaGetSymbolAddress((void**)&g1buf, g_bufG1);

    cudaFuncSetAttribute(fused_kernel,
                         cudaFuncAttributeMaxDynamicSharedMemorySize, SM_TOT);

    fused_kernel<<<GBLK, NTHREADS, SM_TOT>>>(z, w1, b1, w2, b2, bw, nw, nb,
                                             h2buf, g1buf, N_NODES);
    // 16 edges per warp, 8 warps per block -> 128 edges per block
    edge_kernel<<<(N_EDGES + 127) / 128, 256>>>(arcs, g1buf, h2buf, bb, out);
}

// round 13
// speedup vs baseline: 1.6162x; 1.0043x over previous
#include <cuda_runtime.h>
#include <cuda_fp16.h>
#include <cstdint>

#define N_NODES 50000
#define D 128
#define N_EDGES 500000
#define TILE_M 128
#define GBLK ((N_NODES + TILE_M - 1) / TILE_M)
#define NTHREADS 256

// Scratch (no cudaMalloc). H2/G1 stored fp16 (halves edge-gather traffic).
__device__ __half g_bufH2[N_NODES * D];
__device__ __half g_bufG1[N_NODES * D];

// ---- smem (bytes). fp16 tiles, 136 halves/row (272B: 8-row ldmatrix phases
//      hit banks 4i..4i+3 -> conflict-free) ----
#define HS     136
#define SM_ZN  0
#define SM_W1  34816                 // -> H1 after pass 1
#define SM_W2  69632                 // -> bw^T after pass 2
#define SM_PAR 104448                // 512 floats
#define SM_RED 106496                // 512 floats (sum 256 + sq 256)
#define SM_TOT 108544                // x2 CTAs/SM

__device__ __forceinline__ void mma_f16(float& d0, float& d1, float& d2, float& d3,
                                        uint32_t a0, uint32_t a1, uint32_t a2,
                                        uint32_t a3, uint32_t b0, uint32_t b1) {
    asm volatile(
        "mma.sync.aligned.m16n8k16.row.col.f32.f16.f16.f32 "
        "{%0,%1,%2,%3}, {%4,%5,%6,%7}, {%8,%9}, {%0,%1,%2,%3};"
        : "+f"(d0), "+f"(d1), "+f"(d2), "+f"(d3)
        : "r"(a0), "r"(a1), "r"(a2), "r"(a3), "r"(b0), "r"(b1));
}

#define LDMATRIX_X4(r0, r1, r2, r3, addr)                                   \
    asm volatile(                                                           \
        "ldmatrix.sync.aligned.m8n8.x4.shared.b16 {%0,%1,%2,%3}, [%4];"     \
        : "=r"(r0), "=r"(r1), "=r"(r2), "=r"(r3) : "r"(addr))

__device__ __forceinline__ uint32_t smem_u32(const void* p) {
    return (uint32_t)__cvta_generic_to_shared(p);
}

__device__ __forceinline__ float warp_sum(float v) {
#pragma unroll
    for (int o = 16; o > 0; o >>= 1) v += __shfl_xor_sync(0xffffffffu, v, o);
    return v;
}

// Mainloop: warp tile 32 rows x 64 cols, fp16 operands, fp32 acc.
// Fragments via ldmatrix.x4 (6 instrs/kk instead of 24 LDS.32).
__device__ __forceinline__ void mma_pass(const __half* __restrict__ A,
                                         const __half* __restrict__ B,
                                         float acc[2][8][4],
                                         int wr, int wc, int lane) {
#pragma unroll
    for (int rt = 0; rt < 2; rt++)
#pragma unroll
        for (int nt = 0; nt < 8; nt++)
#pragma unroll
            for (int j = 0; j < 4; j++) acc[rt][nt][j] = 0.f;

    // A: matrices 0..3 = rows [ra..+7]@k0, [ra+8..+15]@k0, [ra..+7]@k0+8,
    //    [ra+8..+15]@k0+8  -> lane: row ra+(lane&15), col (lane>>4)*8
    const int a_row_off = lane & 15;
    const int a_col     = (lane >> 4) * 8;
    // B (per nt-pair p): matrices = b0(nt=2p)@k0, b1(2p)@k0+8, b0(2p+1)@k0,
    //    b1(2p+1)@k0+8 -> lane: row (lane&7)+((lane>=16)?8:0), col (lane&8)?8:0
    const int b_row_off = (lane & 7) + ((lane >= 16) ? 8 : 0);
    const int b_col     = (lane & 8) ? 8 : 0;

    uint32_t aAddr[2], bAddr[4];
#pragma unroll
    for (int rt = 0; rt < 2; rt++)
        aAddr[rt] = smem_u32(&A[(wr * 32 + rt * 16 + a_row_off) * HS + a_col]);
#pragma unroll
    for (int p = 0; p < 4; p++)
        bAddr[p] = smem_u32(&B[(wc * 64 + p * 16 + b_row_off) * HS + b_col]);

#pragma unroll
    for (int kk = 0; kk < 8; kk++) {
        const uint32_t koff = kk * 32;  // 16 halves
        uint32_t a[2][4];
        LDMATRIX_X4(a[0][0], a[0][1], a[0][2], a[0][3], aAddr[0] + koff);
        LDMATRIX_X4(a[1][0], a[1][1], a[1][2], a[1][3], aAddr[1] + koff);
        uint32_t b[4][4];
#pragma unroll
        for (int p = 0; p < 4; p++)
            LDMATRIX_X4(b[p][0], b[p][1], b[p][2], b[p][3], bAddr[p] + koff);
#pragma unroll
        for (int p = 0; p < 4; p++)
#pragma unroll
            for (int sub = 0; sub < 2; sub++) {
                int nt = 2 * p + sub;
                uint32_t b0 = b[p][2 * sub], b1 = b[p][2 * sub + 1];
#pragma unroll
                for (int rt = 0; rt < 2; rt++)
                    mma_f16(acc[rt][nt][0], acc[rt][nt][1], acc[rt][nt][2],
                            acc[rt][nt][3], a[rt][0], a[rt][1], a[rt][2],
                            a[rt][3], b0, b1);
            }
    }
}

// relu+bias+LN epilogue. TO_SMEM: fp16 -> H1 smem region; else fp16 -> gmem.
template <bool TO_SMEM>
__device__ __forceinline__ void epilogue_ln(
    float acc[2][8][4], const float* __restrict__ s_bias,
    const float* __restrict__ s_nw, const float* __restrict__ s_nb,
    float* __restrict__ red_sum, float* __restrict__ red_sq,
    __half* __restrict__ H1, __half* __restrict__ gout,
    int row0, int nrows, int wr, int wc, int q, int tig) {
    float sums[2][2], sqs[2][2];
#pragma unroll
    for (int rt = 0; rt < 2; rt++) {
        sums[rt][0] = sums[rt][1] = sqs[rt][0] = sqs[rt][1] = 0.f;
#pragma unroll
        for (int nt = 0; nt < 8; nt++) {
            int c = wc * 64 + nt * 8 + 2 * tig;
            float x0 = fmaxf(acc[rt][nt][0] + s_bias[c], 0.f);
            float x1 = fmaxf(acc[rt][nt][1] + s_bias[c + 1], 0.f);
            float y0 = fmaxf(acc[rt][nt][2] + s_bias[c], 0.f);
            float y1 = fmaxf(acc[rt][nt][3] + s_bias[c + 1], 0.f);
            acc[rt][nt][0] = x0; acc[rt][nt][1] = x1;
            acc[rt][nt][2] = y0; acc[rt][nt][3] = y1;
            sums[rt][0] += x0 + x1; sqs[rt][0] += x0 * x0 + x1 * x1;
            sums[rt][1] += y0 + y1; sqs[rt][1] += y0 * y0 + y1 * y1;
        }
    }
#pragma unroll
    for (int o = 1; o <= 2; o <<= 1)
#pragma unroll
        for (int rt = 0; rt < 2; rt++)
#pragma unroll
            for (int h = 0; h < 2; h++) {
                sums[rt][h] += __shfl_xor_sync(0xffffffffu, sums[rt][h], o);
                sqs[rt][h]  += __shfl_xor_sync(0xffffffffu, sqs[rt][h], o);
            }
    if (tig == 0) {
#pragma unroll
        for (int rt = 0; rt < 2; rt++)
#pragma unroll
            for (int h = 0; h < 2; h++) {
                int r = wr * 32 + rt * 16 + q + h * 8;
                red_sum[wc * 128 + r] = sums[rt][h];
                red_sq[wc * 128 + r]  = sqs[rt][h];
            }
    }
    __syncthreads();
    float mu[2][2], rs[2][2];
#pragma unroll
    for (int rt = 0; rt < 2; rt++)
#pragma unroll
        for (int h = 0; h < 2; h++) {
            int r = wr * 32 + rt * 16 + q + h * 8;
            float ts = red_sum[r] + red_sum[128 + r];
            float tq = red_sq[r] + red_sq[128 + r];
            float m = ts * (1.0f / 128.0f);
            mu[rt][h] = m;
            rs[rt][h] = rsqrtf(tq * (1.0f / 128.0f) - m * m + 1e-5f);
        }
#pragma unroll
    for (int nt = 0; nt < 8; nt++) {
        int c = wc * 64 + nt * 8 + 2 * tig;
        float nw0 = s_nw[c], nw1 = s_nw[c + 1];
        float nb0 = s_nb[c], nb1 = s_nb[c + 1];
#pragma unroll
        for (int rt = 0; rt < 2; rt++)
#pragma unroll
            for (int h = 0; h < 2; h++) {
                int r = wr * 32 + rt * 16 + q + h * 8;
                float v0 = (acc[rt][nt][2 * h]     - mu[rt][h]) * rs[rt][h] * nw0 + nb0;
                float v1 = (acc[rt][nt][2 * h + 1] - mu[rt][h]) * rs[rt][h] * nw1 + nb1;
                if (TO_SMEM) {
                    *reinterpret_cast<__half2*>(&H1[r * HS + c]) =
                        __floats2half2_rn(v0, v1);
                } else {
                    int gr = row0 + r;
                    if (gr < nrows)
                        *reinterpret_cast<__half2*>(gout + (size_t)gr * D + c) =
                            __floats2half2_rn(v0, v1);
                }
            }
    }
}

__global__ void __launch_bounds__(NTHREADS, 2) fused_kernel(
    const float* __restrict__ z,
    const float* __restrict__ w1, const float* __restrict__ b1,
    const float* __restrict__ w2, const float* __restrict__ b2,
    const float* __restrict__ bw,
    const float* __restrict__ nw, const float* __restrict__ nb,
    __half* __restrict__ h2_out, __half* __restrict__ g1_out, int nrows) {
    extern __shared__ char smem[];
    __half* ZNh = reinterpret_cast<__half*>(smem + SM_ZN);
    __half* W1h = reinterpret_cast<__half*>(smem + SM_W1);   // -> H1
    __half* W2h = reinterpret_cast<__half*>(smem + SM_W2);   // -> bw^T
    float*  par = reinterpret_cast<float*>(smem + SM_PAR);
    float*  red_sum = reinterpret_cast<float*>(smem + SM_RED);
    float*  red_sq  = red_sum + 256;

    const int tid  = threadIdx.x;
    const int lane = tid & 31;
    const int w    = tid >> 5;    // 0..7
    const int q    = lane >> 2;
    const int tig  = lane & 3;
    const int wr   = w & 3;       // 32-row group
    const int wc   = w >> 2;      // 64-col group
    const int row0 = blockIdx.x * TILE_M;

    // ---- params ----
    for (int idx = tid; idx < 512; idx += NTHREADS)
        par[idx] = (idx < 128)   ? b1[idx]
                 : (idx < 256)   ? b2[idx - 128]
                 : (idx < 384)   ? nw[idx - 256]
                                 : nb[idx - 384];

    // ---- stage W1, W2 as fp16 ----
#pragma unroll
    for (int i = 0; i < 16; i++) {
        int idx = tid + i * NTHREADS;
        int r = idx >> 5, c4 = idx & 31;
        float4 v1 = reinterpret_cast<const float4*>(w1)[idx];
        float4 v2 = reinterpret_cast<const float4*>(w2)[idx];
        int off = r * HS + c4 * 4;
        *reinterpret_cast<__half2*>(&W1h[off])     = __floats2half2_rn(v1.x, v1.y);
        *reinterpret_cast<__half2*>(&W1h[off + 2]) = __floats2half2_rn(v1.z, v1.w);
        *reinterpret_cast<__half2*>(&W2h[off])     = __floats2half2_rn(v2.x, v2.y);
        *reinterpret_cast<__half2*>(&W2h[off + 2]) = __floats2half2_rn(v2.z, v2.w);
    }
    __syncthreads();   // par visible for LN below

    // ---- ZN = LN(z) staged directly to fp16 smem (warp w: 16 rows) ----
    {
        const float* s_nw = par + 256;
        const float* s_nb = par + 384;
        float4 w4  = reinterpret_cast<const float4*>(s_nw)[lane];
        float4 nb4 = reinterpret_cast<const float4*>(s_nb)[lane];
#pragma unroll
        for (int i = 0; i < 16; i++) {
            int r = w * 16 + i;
            int gr = row0 + r;
            float4 v = make_float4(0.f, 0.f, 0.f, 0.f);
            if (gr < nrows) v = reinterpret_cast<const float4*>(z)[(size_t)gr * 32 + lane];
            float s  = warp_sum(v.x + v.y + v.z + v.w);
            float sq = warp_sum(v.x * v.x + v.y * v.y + v.z * v.z + v.w * v.w);
            float mu = s * (1.0f / 128.0f);
            float rs = rsqrtf(sq * (1.0f / 128.0f) - mu * mu + 1e-5f);
            float o0 = (v.x - mu) * rs * w4.x + nb4.x;
            float o1 = (v.y - mu) * rs * w4.y + nb4.y;
            float o2 = (v.z - mu) * rs * w4.z + nb4.z;
            float o3 = (v.w - mu) * rs * w4.w + nb4.w;
            int off = r * HS + lane * 4;
            *reinterpret_cast<__half2*>(&ZNh[off])     = __floats2half2_rn(o0, o1);
            *reinterpret_cast<__half2*>(&ZNh[off + 2]) = __floats2half2_rn(o2, o3);
        }
    }
    __syncthreads();

    const float* s_b1 = par;
    const float* s_b2 = par + 128;
    const float* s_nw = par + 256;
    const float* s_nb = par + 384;

    float acc[2][8][4];

    // ===== PASS 1: H1 = LN(relu(ZN @ W1^T + b1)) -> W1 region (fp16) =====
    mma_pass(ZNh, W1h, acc, wr, wc, lane);
    epilogue_ln<true>(acc, s_b1, s_nw, s_nb, red_sum, red_sq, W1h, nullptr,
                      row0, nrows, wr, wc, q, tig);

    // ===== PASS 2: H2 = LN(relu(ZN @ W2^T + b2)) -> gmem (fp16) =====
    mma_pass(ZNh, W2h, acc, wr, wc, lane);
    __syncthreads();   // all warps done reading W2
    // restage W2 region <- bw^T fp16: W2h[f][d] = bw[d][f]
#pragma unroll
    for (int i = 0; i < 64; i++) {
        int idx = tid + i * NTHREADS;
        int d = idx >> 7, f = idx & 127;
        W2h[f * HS + d] = __float2half_rn(bw[idx]);
    }
    epilogue_ln<false>(acc, s_b2, s_nw, s_nb, red_sum, red_sq, nullptr, h2_out,
                       row0, nrows, wr, wc, q, tig);

    // ===== PASS 3: G1 = H1 @ bil_w -> gmem (fp16) =====
    mma_pass(W1h, W2h, acc, wr, wc, lane);
#pragma unroll
    for (int nt = 0; nt < 8; nt++) {
        int c = wc * 64 + nt * 8 + 2 * tig;
#pragma unroll
        for (int rt = 0; rt < 2; rt++)
#pragma unroll
            for (int h = 0; h < 2; h++) {
                int gr = row0 + wr * 32 + rt * 16 + q + h * 8;
                if (gr < nrows)
                    *reinterpret_cast<__half2*>(g1_out + (size_t)gr * D + c) =
                        __floats2half2_rn(acc[rt][nt][2 * h], acc[rt][nt][2 * h + 1]);
            }
    }
}

// ---------------------------------------------------------------------------
// Edge kernel (frozen at R12 config): 16 edges/warp = 4 batches x 4 edges;
// 8 lanes/edge, full 128B wavefronts, 16 independent L2-only loads per lane.
// ---------------------------------------------------------------------------
__global__ void __launch_bounds__(256) edge_kernel(
    const int* __restrict__ arcs,
    const __half* __restrict__ G1,
    const __half* __restrict__ H2,
    const float* __restrict__ bilb,
    float* __restrict__ out) {
    const int warp = (blockIdx.x * blockDim.x + threadIdx.x) >> 5;
    const int lane = threadIdx.x & 31;
    const int j    = lane >> 3;   // edge-in-batch (0..3)
    const int s    = lane & 7;    // sub-lane within edge
    const int e0   = warp * 16 + j;
    if (e0 >= N_EDGES) return;

    int2 a[4];
#pragma unroll
    for (int b = 0; b < 4; b++)
        a[b] = __ldg(reinterpret_cast<const int2*>(arcs) + e0 + 4 * b);

    float4 g[4][2], h[4][2];
#pragma unroll
    for (int b = 0; b < 4; b++) {
        const float4* g4 = reinterpret_cast<const float4*>(G1 + (size_t)a[b].x * D);
        const float4* h4 = reinterpret_cast<const float4*>(H2 + (size_t)a[b].y * D);
        g[b][0] = __ldcg(g4 + s);
        g[b][1] = __ldcg(g4 + s + 8);
        h[b][0] = __ldcg(h4 + s);
        h[b][1] = __ldcg(h4 + s + 8);
    }
#pragma unroll
    for (int b = 0; b < 4; b++) {
        float v = 0.f;
#pragma unroll
        for (int p = 0; p < 2; p++) {
            const __half2* gh = reinterpret_cast<const __half2*>(&g[b][p]);
            const __half2* hh = reinterpret_cast<const __half2*>(&h[b][p]);
#pragma unroll
            for (int k = 0; k < 4; k++) {
                float2 gf = __half22float2(gh[k]);
                float2 hf = __half22float2(hh[k]);
                v += gf.x * hf.x + gf.y * hf.y;
            }
        }
        v += __shfl_xor_sync(0xffffffffu, v, 1);
        v += __shfl_xor_sync(0xffffffffu, v, 2);
        v += __shfl_xor_sync(0xffffffffu, v, 4);
        if (s == 0) out[e0 + 4 * b] = v + bilb[0];
    }
}

// ---------------------------------------------------------------------------
extern "C" void kernel_launch(void* const* d_in, const int* in_sizes, int n_in,
                              void* d_out, int out_size) {
    const float* z    = (const float*)d_in[0];
    const int*   arcs = (const int*)d_in[1];
    const float* w1   = (const float*)d_in[2];
    const float* b1   = (const float*)d_in[3];
    const float* w2   = (const float*)d_in[4];
    const float* b2   = (const float*)d_in[5];
    const float* bw   = (const float*)d_in[6];
    const float* bb   = (const float*)d_in[7];
    const float* nw   = (const float*)d_in[8];
    const float* nb   = (const float*)d_in[9];
    float*       out  = (float*)d_out;

    __half *h2buf, *g1buf;
    cudaGetSymbolAddress((void**)&h2buf, g_bufH2);
    cudaGetSymbolAddress((void**)&g1buf, g_bufG1);

    cudaFuncSetAttribute(fused_kernel,
                         cudaFuncAttributeMaxDynamicSharedMemorySize, SM_TOT);

    fused_kernel<<<GBLK, NTHREADS, SM_TOT>>>(z, w1, b1, w2, b2, bw, nw, nb,
                                             h2buf, g1buf, N_NODES);
    // 16 edges per warp, 8 warps per block -> 128 edges per block
    edge_kernel<<<(N_EDGES + 127) / 128, 256>>>(arcs, g1buf, h2buf, bb, out);
}

// round 14
// speedup vs baseline: 1.7379x; 1.0753x over previous
#include <cuda_runtime.h>
#include <cuda_fp16.h>
#include <cstdint>

#define N_NODES 50000
#define D 128
#define N_EDGES 500000
#define TILE_M 128
#define NTILES ((N_NODES + TILE_M - 1) / TILE_M)   // 391
#define GRID   148
#define NTHREADS 512

// Scratch (no cudaMalloc). H2/G1 stored fp16 (halves edge-gather traffic).
__device__ __half g_bufH2[N_NODES * D];
__device__ __half g_bufG1[N_NODES * D];

// ---- smem (bytes). fp16 tiles, 136 halves/row (stride 272B: 8-row ldmatrix
//      phases hit banks 4i..4i+3 -> conflict-free) ----
#define HS     136
#define TILE_B (128 * HS * 2)        // 34816
#define SM_ZN  0
#define SM_H1  34816
#define SM_W1  69632
#define SM_W2  104448
#define SM_BW  139264
#define SM_PAR 174080                // 512 floats
#define SM_RED 176128                // 512 floats (sum 256 + sq 256)
#define SM_TOT 178176                // 1 CTA/SM

__device__ __forceinline__ void mma_f16(float& d0, float& d1, float& d2, float& d3,
                                        uint32_t a0, uint32_t a1, uint32_t a2,
                                        uint32_t a3, uint32_t b0, uint32_t b1) {
    asm volatile(
        "mma.sync.aligned.m16n8k16.row.col.f32.f16.f16.f32 "
        "{%0,%1,%2,%3}, {%4,%5,%6,%7}, {%8,%9}, {%0,%1,%2,%3};"
        : "+f"(d0), "+f"(d1), "+f"(d2), "+f"(d3)
        : "r"(a0), "r"(a1), "r"(a2), "r"(a3), "r"(b0), "r"(b1));
}

#define LDMATRIX_X4(r0, r1, r2, r3, addr)                                   \
    asm volatile(                                                           \
        "ldmatrix.sync.aligned.m8n8.x4.shared.b16 {%0,%1,%2,%3}, [%4];"     \
        : "=r"(r0), "=r"(r1), "=r"(r2), "=r"(r3) : "r"(addr))

__device__ __forceinline__ uint32_t smem_u32(const void* p) {
    return (uint32_t)__cvta_generic_to_shared(p);
}

__device__ __forceinline__ float warp_sum(float v) {
#pragma unroll
    for (int o = 16; o > 0; o >>= 1) v += __shfl_xor_sync(0xffffffffu, v, o);
    return v;
}

// Mainloop: warp tile 16 rows x 64 cols, fp16 operands, fp32 acc.
// 16 warps cover the 128x128 tile (wr 0..7 x wc 0..1).
__device__ __forceinline__ void mma_pass(const __half* __restrict__ A,
                                         const __half* __restrict__ B,
                                         float acc[8][4],
                                         int wr, int wc, int lane) {
#pragma unroll
    for (int nt = 0; nt < 8; nt++)
#pragma unroll
        for (int j = 0; j < 4; j++) acc[nt][j] = 0.f;

    const int a_row_off = lane & 15;
    const int a_col     = (lane >> 4) * 8;
    const int b_row_off = (lane & 7) + ((lane >= 16) ? 8 : 0);
    const int b_col     = (lane & 8) ? 8 : 0;

    uint32_t aAddr = smem_u32(&A[(wr * 16 + a_row_off) * HS + a_col]);
    uint32_t bAddr[4];
#pragma unroll
    for (int p = 0; p < 4; p++)
        bAddr[p] = smem_u32(&B[(wc * 64 + p * 16 + b_row_off) * HS + b_col]);

#pragma unroll
    for (int kk = 0; kk < 8; kk++) {
        const uint32_t koff = kk * 32;  // 16 halves
        uint32_t a0, a1, a2, a3;
        LDMATRIX_X4(a0, a1, a2, a3, aAddr + koff);
        uint32_t b[4][4];
#pragma unroll
        for (int p = 0; p < 4; p++)
            LDMATRIX_X4(b[p][0], b[p][1], b[p][2], b[p][3], bAddr[p] + koff);
#pragma unroll
        for (int p = 0; p < 4; p++)
#pragma unroll
            for (int sub = 0; sub < 2; sub++) {
                int nt = 2 * p + sub;
                mma_f16(acc[nt][0], acc[nt][1], acc[nt][2], acc[nt][3],
                        a0, a1, a2, a3, b[p][2 * sub], b[p][2 * sub + 1]);
            }
    }
}

// relu+bias+LN epilogue (16-row warp tile). TO_SMEM: fp16 -> H1; else gmem.
template <bool TO_SMEM>
__device__ __forceinline__ void epilogue_ln(
    float acc[8][4], const float* __restrict__ s_bias,
    const float* __restrict__ s_nw, const float* __restrict__ s_nb,
    float* __restrict__ red_sum, float* __restrict__ red_sq,
    __half* __restrict__ H1, __half* __restrict__ gout,
    int row0, int nrows, int wr, int wc, int q, int tig) {
    float sums[2] = {0.f, 0.f}, sqs[2] = {0.f, 0.f};
#pragma unroll
    for (int nt = 0; nt < 8; nt++) {
        int c = wc * 64 + nt * 8 + 2 * tig;
        float x0 = fmaxf(acc[nt][0] + s_bias[c], 0.f);
        float x1 = fmaxf(acc[nt][1] + s_bias[c + 1], 0.f);
        float y0 = fmaxf(acc[nt][2] + s_bias[c], 0.f);
        float y1 = fmaxf(acc[nt][3] + s_bias[c + 1], 0.f);
        acc[nt][0] = x0; acc[nt][1] = x1; acc[nt][2] = y0; acc[nt][3] = y1;
        sums[0] += x0 + x1; sqs[0] += x0 * x0 + x1 * x1;
        sums[1] += y0 + y1; sqs[1] += y0 * y0 + y1 * y1;
    }
#pragma unroll
    for (int o = 1; o <= 2; o <<= 1)
#pragma unroll
        for (int h = 0; h < 2; h++) {
            sums[h] += __shfl_xor_sync(0xffffffffu, sums[h], o);
            sqs[h]  += __shfl_xor_sync(0xffffffffu, sqs[h], o);
        }
    if (tig == 0) {
#pragma unroll
        for (int h = 0; h < 2; h++) {
            int r = wr * 16 + q + h * 8;
            red_sum[wc * 128 + r] = sums[h];
            red_sq[wc * 128 + r]  = sqs[h];
        }
    }
    __syncthreads();
    float mu[2], rs[2];
#pragma unroll
    for (int h = 0; h < 2; h++) {
        int r = wr * 16 + q + h * 8;
        float ts = red_sum[r] + red_sum[128 + r];
        float tq = red_sq[r] + red_sq[128 + r];
        float m = ts * (1.0f / 128.0f);
        mu[h] = m;
        rs[h] = rsqrtf(tq * (1.0f / 128.0f) - m * m + 1e-5f);
    }
#pragma unroll
    for (int nt = 0; nt < 8; nt++) {
        int c = wc * 64 + nt * 8 + 2 * tig;
        float nw0 = s_nw[c], nw1 = s_nw[c + 1];
        float nb0 = s_nb[c], nb1 = s_nb[c + 1];
#pragma unroll
        for (int h = 0; h < 2; h++) {
            int r = wr * 16 + q + h * 8;
            float v0 = (acc[nt][2 * h]     - mu[h]) * rs[h] * nw0 + nb0;
            float v1 = (acc[nt][2 * h + 1] - mu[h]) * rs[h] * nw1 + nb1;
            if (TO_SMEM) {
                *reinterpret_cast<__half2*>(&H1[r * HS + c]) =
                    __floats2half2_rn(v0, v1);
            } else {
                int gr = row0 + r;
                if (gr < nrows)
                    *reinterpret_cast<__half2*>(gout + (size_t)gr * D + c) =
                        __floats2half2_rn(v0, v1);
            }
        }
    }
}

// Persistent fused kernel: 148 CTAs x 512 threads, all weights resident.
__global__ void __launch_bounds__(NTHREADS, 1) fused_kernel(
    const float* __restrict__ z,
    const float* __restrict__ w1, const float* __restrict__ b1,
    const float* __restrict__ w2, const float* __restrict__ b2,
    const float* __restrict__ bw,
    const float* __restrict__ nw, const float* __restrict__ nb,
    __half* __restrict__ h2_out, __half* __restrict__ g1_out, int nrows) {
    extern __shared__ char smem[];
    __half* ZNh = reinterpret_cast<__half*>(smem + SM_ZN);
    __half* H1h = reinterpret_cast<__half*>(smem + SM_H1);
    __half* W1h = reinterpret_cast<__half*>(smem + SM_W1);
    __half* W2h = reinterpret_cast<__half*>(smem + SM_W2);
    __half* BWh = reinterpret_cast<__half*>(smem + SM_BW);
    float*  par = reinterpret_cast<float*>(smem + SM_PAR);
    float*  red_sum = reinterpret_cast<float*>(smem + SM_RED);
    float*  red_sq  = red_sum + 256;

    const int tid  = threadIdx.x;
    const int lane = tid & 31;
    const int w    = tid >> 5;    // 0..15
    const int q    = lane >> 2;
    const int tig  = lane & 3;
    const int wr   = w & 7;       // 16-row group
    const int wc   = w >> 3;      // 64-col group

    // ---- stage ALL weights + params ONCE ----
    if (tid < 512)
        par[tid] = (tid < 128)   ? b1[tid]
                 : (tid < 256)   ? b2[tid - 128]
                 : (tid < 384)   ? nw[tid - 256]
                                 : nb[tid - 384];
#pragma unroll
    for (int i = 0; i < 8; i++) {
        int idx = tid + i * NTHREADS;
        int r = idx >> 5, c4 = idx & 31;
        float4 v1 = reinterpret_cast<const float4*>(w1)[idx];
        float4 v2 = reinterpret_cast<const float4*>(w2)[idx];
        int off = r * HS + c4 * 4;
        *reinterpret_cast<__half2*>(&W1h[off])     = __floats2half2_rn(v1.x, v1.y);
        *reinterpret_cast<__half2*>(&W1h[off + 2]) = __floats2half2_rn(v1.z, v1.w);
        *reinterpret_cast<__half2*>(&W2h[off])     = __floats2half2_rn(v2.x, v2.y);
        *reinterpret_cast<__half2*>(&W2h[off + 2]) = __floats2half2_rn(v2.z, v2.w);
    }
    // BW^T: BWh[f][d] = bw[d][f]
#pragma unroll
    for (int i = 0; i < 32; i++) {
        int idx = tid + i * NTHREADS;
        int d = idx >> 7, f = idx & 127;
        BWh[f * HS + d] = __float2half_rn(bw[idx]);
    }
    __syncthreads();

    const float* s_b1 = par;
    const float* s_b2 = par + 128;
    const float* s_nw = par + 256;
    const float* s_nb = par + 384;

    float4 lnw4 = reinterpret_cast<const float4*>(s_nw)[lane];
    float4 lnb4 = reinterpret_cast<const float4*>(s_nb)[lane];

    // ---- persistent tile loop ----
    for (int t = blockIdx.x; t < NTILES; t += GRID) {
        const int row0 = t * TILE_M;

        // LN(z) staged to fp16 ZN (warp w: rows w*8 .. w*8+7; 2 MLP-4 batches)
#pragma unroll
        for (int bb2 = 0; bb2 < 2; bb2++) {
            float4 v[4];
#pragma unroll
            for (int i = 0; i < 4; i++) {
                int gr = row0 + w * 8 + bb2 * 4 + i;
                v[i] = (gr < nrows)
                         ? reinterpret_cast<const float4*>(z)[(size_t)gr * 32 + lane]
                         : make_float4(0.f, 0.f, 0.f, 0.f);
            }
#pragma unroll
            for (int i = 0; i < 4; i++) {
                int r = w * 8 + bb2 * 4 + i;
                float s  = warp_sum(v[i].x + v[i].y + v[i].z + v[i].w);
                float sq = warp_sum(v[i].x * v[i].x + v[i].y * v[i].y +
                                    v[i].z * v[i].z + v[i].w * v[i].w);
                float mu = s * (1.0f / 128.0f);
                float rs = rsqrtf(sq * (1.0f / 128.0f) - mu * mu + 1e-5f);
                float o0 = (v[i].x - mu) * rs * lnw4.x + lnb4.x;
                float o1 = (v[i].y - mu) * rs * lnw4.y + lnb4.y;
                float o2 = (v[i].z - mu) * rs * lnw4.z + lnb4.z;
                float o3 = (v[i].w - mu) * rs * lnw4.w + lnb4.w;
                int off = r * HS + lane * 4;
                *reinterpret_cast<__half2*>(&ZNh[off])     = __floats2half2_rn(o0, o1);
                *reinterpret_cast<__half2*>(&ZNh[off + 2]) = __floats2half2_rn(o2, o3);
            }
        }
        __syncthreads();   // ZN ready (also: all warps done with prior pass3)

        float acc[8][4];

        // PASS 1: H1 = LN(relu(ZN @ W1^T + b1)) -> H1 smem (fp16)
        mma_pass(ZNh, W1h, acc, wr, wc, lane);
        epilogue_ln<true>(acc, s_b1, s_nw, s_nb, red_sum, red_sq, H1h, nullptr,
                          row0, nrows, wr, wc, q, tig);
        __syncthreads();   // H1 visible; red arrays free for epilogue 2

        // PASS 2: H2 = LN(relu(ZN @ W2^T + b2)) -> gmem (fp16)
        mma_pass(ZNh, W2h, acc, wr, wc, lane);
        epilogue_ln<false>(acc, s_b2, s_nw, s_nb, red_sum, red_sq, nullptr,
                           h2_out, row0, nrows, wr, wc, q, tig);

        // PASS 3: G1 = H1 @ bil_w -> gmem (fp16)
        mma_pass(H1h, BWh, acc, wr, wc, lane);
#pragma unroll
        for (int nt = 0; nt < 8; nt++) {
            int c = wc * 64 + nt * 8 + 2 * tig;
#pragma unroll
            for (int h = 0; h < 2; h++) {
                int gr = row0 + wr * 16 + q + h * 8;
                if (gr < nrows)
                    *reinterpret_cast<__half2*>(g1_out + (size_t)gr * D + c) =
                        __floats2half2_rn(acc[nt][2 * h], acc[nt][2 * h + 1]);
            }
        }
        // next iter's LN-sync fences ZN overwrite vs pass2 reads and H1
        // overwrite vs pass3 reads.
    }
}

// ---------------------------------------------------------------------------
// Edge kernel (frozen at R12 config — at L2 roofline): 16 edges/warp,
// 8 lanes/edge, full 128B wavefronts, 16 independent L2-only loads per lane.
// ---------------------------------------------------------------------------
__global__ void __launch_bounds__(256) edge_kernel(
    const int* __restrict__ arcs,
    const __half* __restrict__ G1,
    const __half* __restrict__ H2,
    const float* __restrict__ bilb,
    float* __restrict__ out) {
    const int warp = (blockIdx.x * blockDim.x + threadIdx.x) >> 5;
    const int lane = threadIdx.x & 31;
    const int j    = lane >> 3;
    const int s    = lane & 7;
    const int e0   = warp * 16 + j;
    if (e0 >= N_EDGES) return;

    int2 a[4];
#pragma unroll
    for (int b = 0; b < 4; b++)
        a[b] = __ldg(reinterpret_cast<const int2*>(arcs) + e0 + 4 * b);

    float4 g[4][2], h[4][2];
#pragma unroll
    for (int b = 0; b < 4; b++) {
        const float4* g4 = reinterpret_cast<const float4*>(G1 + (size_t)a[b].x * D);
        const float4* h4 = reinterpret_cast<const float4*>(H2 + (size_t)a[b].y * D);
        g[b][0] = __ldcg(g4 + s);
        g[b][1] = __ldcg(g4 + s + 8);
        h[b][0] = __ldcg(h4 + s);
        h[b][1] = __ldcg(h4 + s + 8);
    }
#pragma unroll
    for (int b = 0; b < 4; b++) {
        float v = 0.f;
#pragma unroll
        for (int p = 0; p < 2; p++) {
            const __half2* gh = reinterpret_cast<const __half2*>(&g[b][p]);
            const __half2* hh = reinterpret_cast<const __half2*>(&h[b][p]);
#pragma unroll
            for (int k = 0; k < 4; k++) {
                float2 gf = __half22float2(gh[k]);
                float2 hf = __half22float2(hh[k]);
                v += gf.x * hf.x + gf.y * hf.y;
            }
        }
        v += __shfl_xor_sync(0xffffffffu, v, 1);
        v += __shfl_xor_sync(0xffffffffu, v, 2);
        v += __shfl_xor_sync(0xffffffffu, v, 4);
        if (s == 0) out[e0 + 4 * b] = v + bilb[0];
    }
}

// ---------------------------------------------------------------------------
extern "C" void kernel_launch(void* const* d_in, const int* in_sizes, int n_in,
                              void* d_out, int out_size) {
    const float* z    = (const float*)d_in[0];
    const int*   arcs = (const int*)d_in[1];
    const float* w1   = (const float*)d_in[2];
    const float* b1   = (const float*)d_in[3];
    const float* w2   = (const float*)d_in[4];
    const float* b2   = (const float*)d_in[5];
    const float* bw   = (const float*)d_in[6];
    const float* bb   = (const float*)d_in[7];
    const float* nw   = (const float*)d_in[8];
    const float* nb   = (const float*)d_in[9];
    float*       out  = (float*)d_out;

    __half *h2buf, *g1buf;
    cudaGetSymbolAddress((void**)&h2buf, g_bufH2);
    cudaGetSymbolAddress((void**)&g1buf, g_bufG1);

    cudaFuncSetAttribute(fused_kernel,
                         cudaFuncAttributeMaxDynamicSharedMemorySize, SM_TOT);

    fused_kernel<<<GRID, NTHREADS, SM_TOT>>>(z, w1, b1, w2, b2, bw, nw, nb,
                                             h2buf, g1buf, N_NODES);
    // 16 edges per warp, 8 warps per block -> 128 edges per block
    edge_kernel<<<(N_EDGES + 127) / 128, 256>>>(arcs, g1buf, h2buf, bb, out);
}

// round 15
// speedup vs baseline: 1.7925x; 1.0314x over previous
#include <cuda_runtime.h>
#include <cuda_fp16.h>
#include <cstdint>

#define N_NODES 50000
#define D 128
#define N_EDGES 500000
#define TILE_M 128
#define NTILES ((N_NODES + TILE_M - 1) / TILE_M)   // 391
#define GRID   148
#define NTHREADS 512

// Scratch (no cudaMalloc). H2/G1 stored fp16 (halves edge-gather traffic).
__device__ __half g_bufH2[N_NODES * D];
__device__ __half g_bufG1[N_NODES * D];

// ---- smem (bytes). fp16 tiles, 136 halves/row ----
#define HS     136
#define SM_ZN  0
#define SM_H1  34816
#define SM_W1  69632
#define SM_W2  104448
#define SM_BW  139264
#define SM_PAR 174080                // 512 floats
#define SM_RED 176128                // 512 floats (sum 256 + sq 256)
#define SM_TOT 178176                // 1 CTA/SM

__device__ __forceinline__ void mma_f16(float& d0, float& d1, float& d2, float& d3,
                                        uint32_t a0, uint32_t a1, uint32_t a2,
                                        uint32_t a3, uint32_t b0, uint32_t b1) {
    asm volatile(
        "mma.sync.aligned.m16n8k16.row.col.f32.f16.f16.f32 "
        "{%0,%1,%2,%3}, {%4,%5,%6,%7}, {%8,%9}, {%0,%1,%2,%3};"
        : "+f"(d0), "+f"(d1), "+f"(d2), "+f"(d3)
        : "r"(a0), "r"(a1), "r"(a2), "r"(a3), "r"(b0), "r"(b1));
}

#define LDMATRIX_X4(r0, r1, r2, r3, addr)                                   \
    asm volatile(                                                           \
        "ldmatrix.sync.aligned.m8n8.x4.shared.b16 {%0,%1,%2,%3}, [%4];"     \
        : "=r"(r0), "=r"(r1), "=r"(r2), "=r"(r3) : "r"(addr))

__device__ __forceinline__ uint32_t smem_u32(const void* p) {
    return (uint32_t)__cvta_generic_to_shared(p);
}

__device__ __forceinline__ float warp_sum(float v) {
#pragma unroll
    for (int o = 16; o > 0; o >>= 1) v += __shfl_xor_sync(0xffffffffu, v, o);
    return v;
}

// Single-B mainloop (pass 3): warp tile 16 rows x 64 cols.
__device__ __forceinline__ void mma_pass(const __half* __restrict__ A,
                                         const __half* __restrict__ B,
                                         float acc[8][4],
                                         int wr, int wc, int lane) {
#pragma unroll
    for (int nt = 0; nt < 8; nt++)
#pragma unroll
        for (int j = 0; j < 4; j++) acc[nt][j] = 0.f;

    const int a_row_off = lane & 15;
    const int a_col     = (lane >> 4) * 8;
    const int b_row_off = (lane & 7) + ((lane >= 16) ? 8 : 0);
    const int b_col     = (lane & 8) ? 8 : 0;

    uint32_t aAddr = smem_u32(&A[(wr * 16 + a_row_off) * HS + a_col]);
    uint32_t bAddr[4];
#pragma unroll
    for (int p = 0; p < 4; p++)
        bAddr[p] = smem_u32(&B[(wc * 64 + p * 16 + b_row_off) * HS + b_col]);

#pragma unroll
    for (int kk = 0; kk < 8; kk++) {
        const uint32_t koff = kk * 32;
        uint32_t a0, a1, a2, a3;
        LDMATRIX_X4(a0, a1, a2, a3, aAddr + koff);
        uint32_t b[4][4];
#pragma unroll
        for (int p = 0; p < 4; p++)
            LDMATRIX_X4(b[p][0], b[p][1], b[p][2], b[p][3], bAddr[p] + koff);
#pragma unroll
        for (int p = 0; p < 4; p++)
#pragma unroll
            for (int sub = 0; sub < 2; sub++) {
                int nt = 2 * p + sub;
                mma_f16(acc[nt][0], acc[nt][1], acc[nt][2], acc[nt][3],
                        a0, a1, a2, a3, b[p][2 * sub], b[p][2 * sub + 1]);
            }
    }
}

// Dual-B mainloop (passes 1+2 fused): A fragments loaded ONCE, two acc sets.
__device__ __forceinline__ void mma_pass_dual(const __half* __restrict__ A,
                                              const __half* __restrict__ B1,
                                              const __half* __restrict__ B2,
                                              float acc1[8][4], float acc2[8][4],
                                              int wr, int wc, int lane) {
#pragma unroll
    for (int nt = 0; nt < 8; nt++)
#pragma unroll
        for (int j = 0; j < 4; j++) { acc1[nt][j] = 0.f; acc2[nt][j] = 0.f; }

    const int a_row_off = lane & 15;
    const int a_col     = (lane >> 4) * 8;
    const int b_row_off = (lane & 7) + ((lane >= 16) ? 8 : 0);
    const int b_col     = (lane & 8) ? 8 : 0;

    uint32_t aAddr = smem_u32(&A[(wr * 16 + a_row_off) * HS + a_col]);
    uint32_t b1Addr[4], b2Addr[4];
#pragma unroll
    for (int p = 0; p < 4; p++) {
        int roff = (wc * 64 + p * 16 + b_row_off) * HS + b_col;
        b1Addr[p] = smem_u32(&B1[roff]);
        b2Addr[p] = smem_u32(&B2[roff]);
    }

#pragma unroll
    for (int kk = 0; kk < 8; kk++) {
        const uint32_t koff = kk * 32;
        uint32_t a0, a1, a2, a3;
        LDMATRIX_X4(a0, a1, a2, a3, aAddr + koff);
        // W1 set
#pragma unroll
        for (int p = 0; p < 4; p++) {
            uint32_t b0r, b1r, b2r, b3r;
            LDMATRIX_X4(b0r, b1r, b2r, b3r, b1Addr[p] + koff);
            mma_f16(acc1[2*p][0], acc1[2*p][1], acc1[2*p][2], acc1[2*p][3],
                    a0, a1, a2, a3, b0r, b1r);
            mma_f16(acc1[2*p+1][0], acc1[2*p+1][1], acc1[2*p+1][2], acc1[2*p+1][3],
                    a0, a1, a2, a3, b2r, b3r);
        }
        // W2 set
#pragma unroll
        for (int p = 0; p < 4; p++) {
            uint32_t b0r, b1r, b2r, b3r;
            LDMATRIX_X4(b0r, b1r, b2r, b3r, b2Addr[p] + koff);
            mma_f16(acc2[2*p][0], acc2[2*p][1], acc2[2*p][2], acc2[2*p][3],
                    a0, a1, a2, a3, b0r, b1r);
            mma_f16(acc2[2*p+1][0], acc2[2*p+1][1], acc2[2*p+1][2], acc2[2*p+1][3],
                    a0, a1, a2, a3, b2r, b3r);
        }
    }
}

// relu+bias+LN epilogue (16-row warp tile). TO_SMEM: fp16 -> H1; else gmem.
template <bool TO_SMEM>
__device__ __forceinline__ void epilogue_ln(
    float acc[8][4], const float* __restrict__ s_bias,
    const float* __restrict__ s_nw, const float* __restrict__ s_nb,
    float* __restrict__ red_sum, float* __restrict__ red_sq,
    __half* __restrict__ H1, __half* __restrict__ gout,
    int row0, int nrows, int wr, int wc, int q, int tig) {
    float sums[2] = {0.f, 0.f}, sqs[2] = {0.f, 0.f};
#pragma unroll
    for (int nt = 0; nt < 8; nt++) {
        int c = wc * 64 + nt * 8 + 2 * tig;
        float x0 = fmaxf(acc[nt][0] + s_bias[c], 0.f);
        float x1 = fmaxf(acc[nt][1] + s_bias[c + 1], 0.f);
        float y0 = fmaxf(acc[nt][2] + s_bias[c], 0.f);
        float y1 = fmaxf(acc[nt][3] + s_bias[c + 1], 0.f);
        acc[nt][0] = x0; acc[nt][1] = x1; acc[nt][2] = y0; acc[nt][3] = y1;
        sums[0] += x0 + x1; sqs[0] += x0 * x0 + x1 * x1;
        sums[1] += y0 + y1; sqs[1] += y0 * y0 + y1 * y1;
    }
#pragma unroll
    for (int o = 1; o <= 2; o <<= 1)
#pragma unroll
        for (int h = 0; h < 2; h++) {
            sums[h] += __shfl_xor_sync(0xffffffffu, sums[h], o);
            sqs[h]  += __shfl_xor_sync(0xffffffffu, sqs[h], o);
        }
    if (tig == 0) {
#pragma unroll
        for (int h = 0; h < 2; h++) {
            int r = wr * 16 + q + h * 8;
            red_sum[wc * 128 + r] = sums[h];
            red_sq[wc * 128 + r]  = sqs[h];
        }
    }
    __syncthreads();
    float mu[2], rs[2];
#pragma unroll
    for (int h = 0; h < 2; h++) {
        int r = wr * 16 + q + h * 8;
        float ts = red_sum[r] + red_sum[128 + r];
        float tq = red_sq[r] + red_sq[128 + r];
        float m = ts * (1.0f / 128.0f);
        mu[h] = m;
        rs[h] = rsqrtf(tq * (1.0f / 128.0f) - m * m + 1e-5f);
    }
#pragma unroll
    for (int nt = 0; nt < 8; nt++) {
        int c = wc * 64 + nt * 8 + 2 * tig;
        float nw0 = s_nw[c], nw1 = s_nw[c + 1];
        float nb0 = s_nb[c], nb1 = s_nb[c + 1];
#pragma unroll
        for (int h = 0; h < 2; h++) {
            int r = wr * 16 + q + h * 8;
            float v0 = (acc[nt][2 * h]     - mu[h]) * rs[h] * nw0 + nb0;
            float v1 = (acc[nt][2 * h + 1] - mu[h]) * rs[h] * nw1 + nb1;
            if (TO_SMEM) {
                *reinterpret_cast<__half2*>(&H1[r * HS + c]) =
                    __floats2half2_rn(v0, v1);
            } else {
                int gr = row0 + r;
                if (gr < nrows)
                    *reinterpret_cast<__half2*>(gout + (size_t)gr * D + c) =
                        __floats2half2_rn(v0, v1);
            }
        }
    }
}

// Persistent fused kernel: 148 CTAs x 512 threads, all weights resident.
__global__ void __launch_bounds__(NTHREADS, 1) fused_kernel(
    const float* __restrict__ z,
    const float* __restrict__ w1, const float* __restrict__ b1,
    const float* __restrict__ w2, const float* __restrict__ b2,
    const float* __restrict__ bw,
    const float* __restrict__ nw, const float* __restrict__ nb,
    __half* __restrict__ h2_out, __half* __restrict__ g1_out, int nrows) {
    extern __shared__ char smem[];
    __half* ZNh = reinterpret_cast<__half*>(smem + SM_ZN);
    __half* H1h = reinterpret_cast<__half*>(smem + SM_H1);
    __half* W1h = reinterpret_cast<__half*>(smem + SM_W1);
    __half* W2h = reinterpret_cast<__half*>(smem + SM_W2);
    __half* BWh = reinterpret_cast<__half*>(smem + SM_BW);
    float*  par = reinterpret_cast<float*>(smem + SM_PAR);
    float*  red_sum = reinterpret_cast<float*>(smem + SM_RED);
    float*  red_sq  = red_sum + 256;

    const int tid  = threadIdx.x;
    const int lane = tid & 31;
    const int w    = tid >> 5;    // 0..15
    const int q    = lane >> 2;
    const int tig  = lane & 3;
    const int wr   = w & 7;       // 16-row group
    const int wc   = w >> 3;      // 64-col group

    // ---- stage ALL weights + params ONCE ----
    if (tid < 512)
        par[tid] = (tid < 128)   ? b1[tid]
                 : (tid < 256)   ? b2[tid - 128]
                 : (tid < 384)   ? nw[tid - 256]
                                 : nb[tid - 384];
#pragma unroll
    for (int i = 0; i < 8; i++) {
        int idx = tid + i * NTHREADS;
        int r = idx >> 5, c4 = idx & 31;
        float4 v1 = reinterpret_cast<const float4*>(w1)[idx];
        float4 v2 = reinterpret_cast<const float4*>(w2)[idx];
        int off = r * HS + c4 * 4;
        *reinterpret_cast<__half2*>(&W1h[off])     = __floats2half2_rn(v1.x, v1.y);
        *reinterpret_cast<__half2*>(&W1h[off + 2]) = __floats2half2_rn(v1.z, v1.w);
        *reinterpret_cast<__half2*>(&W2h[off])     = __floats2half2_rn(v2.x, v2.y);
        *reinterpret_cast<__half2*>(&W2h[off + 2]) = __floats2half2_rn(v2.z, v2.w);
    }
    // BW^T: BWh[f][d] = bw[d][f]
#pragma unroll
    for (int i = 0; i < 32; i++) {
        int idx = tid + i * NTHREADS;
        int d = idx >> 7, f = idx & 127;
        BWh[f * HS + d] = __float2half_rn(bw[idx]);
    }
    __syncthreads();

    const float* s_b1 = par;
    const float* s_b2 = par + 128;
    const float* s_nw = par + 256;
    const float* s_nb = par + 384;

    float4 lnw4 = reinterpret_cast<const float4*>(s_nw)[lane];
    float4 lnb4 = reinterpret_cast<const float4*>(s_nb)[lane];

    // ---- persistent tile loop ----
    for (int t = blockIdx.x; t < NTILES; t += GRID) {
        const int row0 = t * TILE_M;

        // LN(z) staged to fp16 ZN (warp w: rows w*8 .. w*8+7; 2 MLP-4 batches)
#pragma unroll
        for (int bb2 = 0; bb2 < 2; bb2++) {
            float4 v[4];
#pragma unroll
            for (int i = 0; i < 4; i++) {
                int gr = row0 + w * 8 + bb2 * 4 + i;
                v[i] = (gr < nrows)
                         ? reinterpret_cast<const float4*>(z)[(size_t)gr * 32 + lane]
                         : make_float4(0.f, 0.f, 0.f, 0.f);
            }
#pragma unroll
            for (int i = 0; i < 4; i++) {
                int r = w * 8 + bb2 * 4 + i;
                float s  = warp_sum(v[i].x + v[i].y + v[i].z + v[i].w);
                float sq = warp_sum(v[i].x * v[i].x + v[i].y * v[i].y +
                                    v[i].z * v[i].z + v[i].w * v[i].w);
                float mu = s * (1.0f / 128.0f);
                float rs = rsqrtf(sq * (1.0f / 128.0f) - mu * mu + 1e-5f);
                float o0 = (v[i].x - mu) * rs * lnw4.x + lnb4.x;
                float o1 = (v[i].y - mu) * rs * lnw4.y + lnb4.y;
                float o2 = (v[i].z - mu) * rs * lnw4.z + lnb4.z;
                float o3 = (v[i].w - mu) * rs * lnw4.w + lnb4.w;
                int off = r * HS + lane * 4;
                *reinterpret_cast<__half2*>(&ZNh[off])     = __floats2half2_rn(o0, o1);
                *reinterpret_cast<__half2*>(&ZNh[off + 2]) = __floats2half2_rn(o2, o3);
            }
        }
        __syncthreads();   // ZN ready (also fences prior pass3 H1 reads)

        float acc1[8][4], acc2[8][4];

        // PASSES 1+2 fused: H1raw (W1) and H2raw (W2) off one A-fragment load
        mma_pass_dual(ZNh, W1h, W2h, acc1, acc2, wr, wc, lane);

        // epilogue 1: relu+b1+LN -> H1 smem (fp16)
        epilogue_ln<true>(acc1, s_b1, s_nw, s_nb, red_sum, red_sq, H1h, nullptr,
                          row0, nrows, wr, wc, q, tig);
        __syncthreads();   // H1 visible; red arrays free for epilogue 2

        // epilogue 2: relu+b2+LN -> gmem H2 (fp16)
        epilogue_ln<false>(acc2, s_b2, s_nw, s_nb, red_sum, red_sq, nullptr,
                           h2_out, row0, nrows, wr, wc, q, tig);

        // PASS 3: G1 = H1 @ bil_w -> gmem (fp16)
        mma_pass(H1h, BWh, acc1, wr, wc, lane);
#pragma unroll
        for (int nt = 0; nt < 8; nt++) {
            int c = wc * 64 + nt * 8 + 2 * tig;
#pragma unroll
            for (int h = 0; h < 2; h++) {
                int gr = row0 + wr * 16 + q + h * 8;
                if (gr < nrows)
                    *reinterpret_cast<__half2*>(g1_out + (size_t)gr * D + c) =
                        __floats2half2_rn(acc1[nt][2 * h], acc1[nt][2 * h + 1]);
            }
        }
    }
}

// ---------------------------------------------------------------------------
// Edge kernel (frozen — at L2 roofline): 16 edges/warp, 8 lanes/edge,
// full 128B wavefronts, 16 independent L2-only loads per lane.
// ---------------------------------------------------------------------------
__global__ void __launch_bounds__(256) edge_kernel(
    const int* __restrict__ arcs,
    const __half* __restrict__ G1,
    const __half* __restrict__ H2,
    const float* __restrict__ bilb,
    float* __restrict__ out) {
    const int warp = (blockIdx.x * blockDim.x + threadIdx.x) >> 5;
    const int lane = threadIdx.x & 31;
    const int j    = lane >> 3;
    const int s    = lane & 7;
    const int e0   = warp * 16 + j;
    if (e0 >= N_EDGES) return;

    int2 a[4];
#pragma unroll
    for (int b = 0; b < 4; b++)
        a[b] = __ldg(reinterpret_cast<const int2*>(arcs) + e0 + 4 * b);

    float4 g[4][2], h[4][2];
#pragma unroll
    for (int b = 0; b < 4; b++) {
        const float4* g4 = reinterpret_cast<const float4*>(G1 + (size_t)a[b].x * D);
        const float4* h4 = reinterpret_cast<const float4*>(H2 + (size_t)a[b].y * D);
        g[b][0] = __ldcg(g4 + s);
        g[b][1] = __ldcg(g4 + s + 8);
        h[b][0] = __ldcg(h4 + s);
        h[b][1] = __ldcg(h4 + s + 8);
    }
#pragma unroll
    for (int b = 0; b < 4; b++) {
        float v = 0.f;
#pragma unroll
        for (int p = 0; p < 2; p++) {
            const __half2* gh = reinterpret_cast<const __half2*>(&g[b][p]);
            const __half2* hh = reinterpret_cast<const __half2*>(&h[b][p]);
#pragma unroll
            for (int k = 0; k < 4; k++) {
                float2 gf = __half22float2(gh[k]);
                float2 hf = __half22float2(hh[k]);
                v += gf.x * hf.x + gf.y * hf.y;
            }
        }
        v += __shfl_xor_sync(0xffffffffu, v, 1);
        v += __shfl_xor_sync(0xffffffffu, v, 2);
        v += __shfl_xor_sync(0xffffffffu, v, 4);
        if (s == 0) out[e0 + 4 * b] = v + bilb[0];
    }
}

// ---------------------------------------------------------------------------
extern "C" void kernel_launch(void* const* d_in, const int* in_sizes, int n_in,
                              void* d_out, int out_size) {
    const float* z    = (const float*)d_in[0];
    const int*   arcs = (const int*)d_in[1];
    const float* w1   = (const float*)d_in[2];
    const float* b1   = (const float*)d_in[3];
    const float* w2   = (const float*)d_in[4];
    const float* b2   = (const float*)d_in[5];
    const float* bw   = (const float*)d_in[6];
    const float* bb   = (const float*)d_in[7];
    const float* nw   = (const float*)d_in[8];
    const float* nb   = (const float*)d_in[9];
    float*       out  = (float*)d_out;

    __half *h2buf, *g1buf;
    cudaGetSymbolAddress((void**)&h2buf, g_bufH2);
    cudaGetSymbolAddress((void**)&g1buf, g_bufG1);

    cudaFuncSetAttribute(fused_kernel,
                         cudaFuncAttributeMaxDynamicSharedMemorySize, SM_TOT);

    fused_kernel<<<GRID, NTHREADS, SM_TOT>>>(z, w1, b1, w2, b2, bw, nw, nb,
                                             h2buf, g1buf, N_NODES);
    edge_kernel<<<(N_EDGES + 127) / 128, 256>>>(arcs, g1buf, h2buf, bb, out);
}